// round 1
// baseline (speedup 1.0000x reference)
#include <cuda_runtime.h>
#include <math.h>

// Problem constants
#define BB 4
#define H 512
#define W 512
#define HW (H*W)          // 262144 = 2^18
#define NPIX (BB*HW)      // 1048576
#define NITER 32          // max Zhang-Suen double-steps (early-exit when converged)
#define RED_BLOCKS 1024
#define RED_THREADS 256

// Static device scratch (no allocation allowed)
__device__ unsigned char g_imgA[NPIX];
__device__ unsigned char g_imgB[NPIX];
__device__ float g_L[NPIX];      // per-pixel CE loss
__device__ float g_g2[NPIX];     // vertical distance -> squared
__device__ float g_wexp[NPIX];   // exp(-dist/K)
__device__ int   g_flags[NITER]; // per-double-step "changed" flags
__device__ float g_part[3*RED_BLOCKS];

// ---------------------------------------------------------------------------
// Kernel 1: log-softmax CE loss + argmax image, zero the change flags
// ---------------------------------------------------------------------------
__global__ void k_prep(const float* __restrict__ pred, const int* __restrict__ target)
{
    int tid0 = blockIdx.x * blockDim.x + threadIdx.x;
    if (tid0 < NITER) g_flags[tid0] = 0;
    int stride = gridDim.x * blockDim.x;
    for (int i = tid0; i < NPIX; i += stride) {
        int b  = i >> 18;
        int hw = i & (HW - 1);
        float p0 = pred[((size_t)b * 2    ) * HW + hw];
        float p1 = pred[((size_t)b * 2 + 1) * HW + hw];
        float m   = fmaxf(p0, p1);
        float lse = m + logf(expf(p0 - m) + expf(p1 - m));
        int   t   = target[i];
        g_L[i]    = lse - (t ? p1 : p0);
        g_imgA[i] = (p1 > p0) ? (unsigned char)1 : (unsigned char)0;
    }
}

// ---------------------------------------------------------------------------
// Kernel 2: one Zhang-Suen sub-step. FIRST: A->B, else B->A.
// Early-exits (whole grid) once the previous double-step made no change.
// ---------------------------------------------------------------------------
template<bool FIRST>
__global__ void k_thin(int iter)
{
    if (iter > 0 && g_flags[iter - 1] == 0) return;
    const unsigned char* __restrict__ src = FIRST ? g_imgA : g_imgB;
    unsigned char* __restrict__ dst       = FIRST ? g_imgB : g_imgA;

    int tid0   = blockIdx.x * blockDim.x + threadIdx.x;
    int stride = gridDim.x * blockDim.x;
    for (int i = tid0; i < NPIX; i += stride) {
        int b  = i >> 18;
        int hw = i & (HW - 1);
        int h  = hw >> 9;
        int w  = hw & (W - 1);
        const unsigned char* im = src + (size_t)b * HW;

        int p = im[hw];
        unsigned char out = (unsigned char)p;
        if (p) {
            int up = (h > 0), dn = (h < H - 1), lf = (w > 0), rt = (w < W - 1);
            int P2 = up        ? im[hw - W]     : 0;
            int P3 = (up & rt) ? im[hw - W + 1] : 0;
            int P4 = rt        ? im[hw + 1]     : 0;
            int P5 = (dn & rt) ? im[hw + W + 1] : 0;
            int P6 = dn        ? im[hw + W]     : 0;
            int P7 = (dn & lf) ? im[hw + W - 1] : 0;
            int P8 = lf        ? im[hw - 1]     : 0;
            int P9 = (up & lf) ? im[hw - W - 1] : 0;

            int bs = P2 + P3 + P4 + P5 + P6 + P7 + P8 + P9;
            int a  = ((!P2) & P3) + ((!P3) & P4) + ((!P4) & P5) + ((!P5) & P6)
                   + ((!P6) & P7) + ((!P7) & P8) + ((!P8) & P9) + ((!P9) & P2);
            bool c;
            if (FIRST) c = ((P2 & P4 & P6) == 0) && ((P4 & P6 & P8) == 0);
            else       c = ((P2 & P4 & P8) == 0) && ((P2 & P6 & P8) == 0);

            if (bs >= 2 && bs <= 6 && a == 1 && c) {
                out = 0;
                g_flags[iter] = 1;   // benign race: everyone writes 1
            }
        }
        dst[i] = out;
    }
}

// ---------------------------------------------------------------------------
// Kernel 3: capped vertical scans (fwd+bwd) per column -> g2 = min(f,b)^2
// One thread per (batch, column); memory accesses are coalesced across w.
// ---------------------------------------------------------------------------
__global__ void k_vscan()
{
    int i = blockIdx.x * blockDim.x + threadIdx.x;
    if (i >= BB * W) return;
    int b = i >> 9;
    int w = i & (W - 1);
    const unsigned char* im = g_imgA + (size_t)b * HW;
    float* g2 = g_g2 + (size_t)b * HW;

    const float inf1 = (float)(H + W);   // 1024
    float d = inf1;
    for (int h = 0; h < H; h++) {
        d = im[h * W + w] ? 0.0f : fminf(d + 1.0f, inf1);
        g2[h * W + w] = d;
    }
    d = inf1;
    for (int h = H - 1; h >= 0; h--) {
        d = im[h * W + w] ? 0.0f : fminf(d + 1.0f, inf1);
        float v = fminf(d, g2[h * W + w]);
        g2[h * W + w] = v * v;
    }
}

// ---------------------------------------------------------------------------
// Kernel 4: exact row EDT (brute force over q, same formula as reference)
// One block per row; row of g2 staged in shared. Writes exp(-dist/K).
// ---------------------------------------------------------------------------
__global__ void k_edt()
{
    __shared__ float sg[W];
    int row = blockIdx.x;                  // b*H + h, 2048 rows
    const float* g2row = g_g2 + (size_t)row * W;
    int w = threadIdx.x;
    sg[w] = g2row[w];
    __syncthreads();

    float d = 2097152.0f;                  // 2*(H+W)^2
    #pragma unroll 8
    for (int q = 0; q < W; q++) {
        float t = (float)(w - q);
        d = fminf(d, fmaf(t, t, sg[q]));
    }
    float dist = sqrtf(d);
    g_wexp[(size_t)row * W + w] = expf(-dist * 0.05f);   // 1/K_PARAM = 1/20
}

// ---------------------------------------------------------------------------
// Kernel 5: fused endpoints + Wmap*L + 4 direction convs -> 3 partial sums
// ---------------------------------------------------------------------------
__global__ void k_reduce()
{
    float sb = 0.0f, sc = 0.0f, sd = 0.0f;
    int tid0   = blockIdx.x * blockDim.x + threadIdx.x;
    int stride = gridDim.x * blockDim.x;

    for (int i = tid0; i < NPIX; i += stride) {
        int b  = i >> 18;
        int hw = i & (HW - 1);
        int h  = hw >> 9;
        int w  = hw & (W - 1);
        const unsigned char* im = g_imgA + (size_t)b * HW;

        int s  = im[hw];
        int up = (h > 0), dn = (h < H - 1), lf = (w > 0), rt = (w < W - 1);
        int P2 = up        ? im[hw - W]     : 0;
        int P3 = (up & rt) ? im[hw - W + 1] : 0;
        int P4 = rt        ? im[hw + 1]     : 0;
        int P5 = (dn & rt) ? im[hw + W + 1] : 0;
        int P6 = dn        ? im[hw + W]     : 0;
        int P7 = (dn & lf) ? im[hw + W - 1] : 0;
        int P8 = lf        ? im[hw - 1]     : 0;
        int P9 = (up & lf) ? im[hw - W - 1] : 0;

        int cnt = P2 + P3 + P4 + P5 + P6 + P7 + P8 + P9;
        float e  = (s && (cnt == 1 || cnt >= 3)) ? 1.0f : 0.0f;
        float Wm = g_wexp[i] + e * 20.0f;
        sb += Wm * g_L[i];

        float fs  = (float)s;
        float rh  = (float)(P8 + s + P4);
        float rv  = (float)(P2 + s + P6);
        float rd1 = (float)(P9 + s + P5);   // main diagonal
        float rd2 = (float)(P3 + s + P7);   // anti diagonal
        sc += fabsf(rh - fs) + fabsf(rv - fs) + fabsf(rd1 - fs) + fabsf(rd2 - fs);
        sd += fabsf(1.0f - rh) + fabsf(1.0f - rv) + fabsf(1.0f - rd1) + fabsf(1.0f - rd2);
    }

    __shared__ float sh0[RED_THREADS], sh1[RED_THREADS], sh2[RED_THREADS];
    int t = threadIdx.x;
    sh0[t] = sb; sh1[t] = sc; sh2[t] = sd;
    __syncthreads();
    for (int s2 = RED_THREADS / 2; s2 > 0; s2 >>= 1) {
        if (t < s2) {
            sh0[t] += sh0[t + s2];
            sh1[t] += sh1[t + s2];
            sh2[t] += sh2[t + s2];
        }
        __syncthreads();
    }
    if (t == 0) {
        g_part[blockIdx.x]                  = sh0[0];
        g_part[RED_BLOCKS + blockIdx.x]     = sh1[0];
        g_part[2 * RED_BLOCKS + blockIdx.x] = sh2[0];
    }
}

// ---------------------------------------------------------------------------
// Kernel 6: deterministic final sum -> scalar loss
// ---------------------------------------------------------------------------
__global__ void k_final(float* __restrict__ out)
{
    __shared__ float sh0[RED_THREADS], sh1[RED_THREADS], sh2[RED_THREADS];
    int t = threadIdx.x;
    float a = 0.0f, b = 0.0f, c = 0.0f;
    for (int i = t; i < RED_BLOCKS; i += RED_THREADS) {
        a += g_part[i];
        b += g_part[RED_BLOCKS + i];
        c += g_part[2 * RED_BLOCKS + i];
    }
    sh0[t] = a; sh1[t] = b; sh2[t] = c;
    __syncthreads();
    for (int s2 = RED_THREADS / 2; s2 > 0; s2 >>= 1) {
        if (t < s2) {
            sh0[t] += sh0[t + s2];
            sh1[t] += sh1[t + s2];
            sh2[t] += sh2[t + s2];
        }
        __syncthreads();
    }
    if (t == 0) {
        const float invN = 1.0f / (float)NPIX;
        out[0] = sh0[0] * invN + 0.3f * (sh1[0] * invN) + 0.5f * (sh2[0] * invN);
    }
}

// ---------------------------------------------------------------------------
extern "C" void kernel_launch(void* const* d_in, const int* in_sizes, int n_in,
                              void* d_out, int out_size)
{
    const float* pred   = (const float*)d_in[0];
    const int*   target = (const int*)d_in[1];

    k_prep<<<1024, 256>>>(pred, target);

    for (int it = 0; it < NITER; ++it) {
        k_thin<true ><<<1024, 256>>>(it);   // substep 1: A -> B
        k_thin<false><<<1024, 256>>>(it);   // substep 2: B -> A
    }

    k_vscan<<<8, 256>>>();
    k_edt<<<BB * H, W>>>();
    k_reduce<<<RED_BLOCKS, RED_THREADS>>>();
    k_final<<<1, RED_THREADS>>>((float*)d_out);
}

// round 3
// speedup vs baseline: 3.7992x; 3.7992x over previous
#include <cuda_runtime.h>
#include <math.h>

// Problem constants
#define BB 4
#define H 512
#define W 512
#define HW (H*W)          // 262144 = 2^18
#define NPIX (BB*HW)      // 1048576
#define NITER 16          // max Zhang-Suen double-steps (early-exit when converged)
#define RED_BLOCKS 256    // k_reduce: 256 blocks * 256 threads = HW/4 groups exactly
#define RED_THREADS 256

typedef unsigned long long u64;
typedef unsigned int u32;

// Static device scratch (no allocation allowed). 128B-aligned for uint loads.
__device__ __align__(128) unsigned char g_imgA[NPIX];
__device__ __align__(128) unsigned char g_imgB[NPIX];
__device__ float  g_L[NPIX];      // per-pixel CE loss
__device__ float  g_g2[NPIX];     // vertical capped distance squared
__device__ float  g_wexp[NPIX];   // exp(-dist/K)
__device__ int    g_flags[NITER];
__device__ double g_part[3*RED_BLOCKS];

// ---------------------------------------------------------------------------
// Kernel 1: log-softmax CE loss + argmax image, zero the change flags
// ---------------------------------------------------------------------------
__global__ void k_prep(const float* __restrict__ pred, const int* __restrict__ target)
{
    int tid0 = blockIdx.x * blockDim.x + threadIdx.x;
    if (tid0 < NITER) g_flags[tid0] = 0;
    int stride = gridDim.x * blockDim.x;
    for (int i = tid0; i < NPIX; i += stride) {
        int b  = i >> 18;
        int hw = i & (HW - 1);
        float p0 = pred[((size_t)b * 2    ) * HW + hw];
        float p1 = pred[((size_t)b * 2 + 1) * HW + hw];
        float m   = fmaxf(p0, p1);
        float lse = m + logf(expf(p0 - m) + expf(p1 - m));
        int   t   = target[i];
        g_L[i]    = lse - (t ? p1 : p0);
        g_imgA[i] = (p1 > p0) ? (unsigned char)1 : (unsigned char)0;
    }
}

// ---------------------------------------------------------------------------
// 48-bit row window: byte for pixel w0+j sits at bit (j+1)*8; bit 0 byte is
// pixel w0-1; bit 40 byte is pixel w0+4. OOB rows/cols are zero-filled.
// ---------------------------------------------------------------------------
__device__ __forceinline__ u64 winrow(const unsigned char* __restrict__ im, int r, int w0)
{
    if (r < 0 || r >= H) return 0ULL;
    const u32* imu = (const u32*)(im + r * W);
    int c = w0 >> 2;
    u32 C  = imu[c];
    u32 Lw = (w0 > 0)     ? imu[c - 1] : 0u;
    u32 Rw = (w0 + 4 < W) ? imu[c + 1] : 0u;
    return (u64)(Lw >> 24) | ((u64)C << 8) | ((u64)(Rw & 0xFFu) << 40);
}

// ---------------------------------------------------------------------------
// Kernel 2: one Zhang-Suen sub-step, 4 pixels per thread.
// ---------------------------------------------------------------------------
template<bool FIRST>
__global__ void k_thin(int iter)
{
    if (iter > 0 && g_flags[iter - 1] == 0) return;
    const unsigned char* __restrict__ src = FIRST ? g_imgA : g_imgB;
    unsigned char* __restrict__ dst       = FIRST ? g_imgB : g_imgA;

    int t  = blockIdx.x * blockDim.x + threadIdx.x;   // 0..262143 (NPIX/4 groups)
    int b  = t >> 16;                                  // 65536 groups per image
    int g  = t & 65535;
    int h  = g >> 7;                                   // 128 uint-groups per row
    int w0 = (g & 127) << 2;
    const unsigned char* im = src + (size_t)b * HW;

    u64 wa = winrow(im, h - 1, w0);
    u64 wc = winrow(im, h,     w0);
    u64 wb = winrow(im, h + 1, w0);

    u32 outw = 0;
    int changed = 0;
    #pragma unroll
    for (int j = 0; j < 4; j++) {
        int sh = (j + 1) * 8;
        int p  = (int)((wc >> sh) & 1);
        int out = p;
        if (p) {
            int P8 = (int)((wc >> (sh - 8)) & 1), P4 = (int)((wc >> (sh + 8)) & 1);
            int P9 = (int)((wa >> (sh - 8)) & 1), P2 = (int)((wa >> sh) & 1), P3 = (int)((wa >> (sh + 8)) & 1);
            int P7 = (int)((wb >> (sh - 8)) & 1), P6 = (int)((wb >> sh) & 1), P5 = (int)((wb >> (sh + 8)) & 1);

            int bs = P2 + P3 + P4 + P5 + P6 + P7 + P8 + P9;
            int a  = ((P2^1)&P3) + ((P3^1)&P4) + ((P4^1)&P5) + ((P5^1)&P6)
                   + ((P6^1)&P7) + ((P7^1)&P8) + ((P8^1)&P9) + ((P9^1)&P2);
            bool c;
            if (FIRST) c = ((P2 & P4 & P6) == 0) && ((P4 & P6 & P8) == 0);
            else       c = ((P2 & P4 & P8) == 0) && ((P2 & P6 & P8) == 0);

            if (bs >= 2 && bs <= 6 && a == 1 && c) { out = 0; changed = 1; }
        }
        outw |= (u32)out << (j * 8);
    }
    ((u32*)(dst + (size_t)b * HW))[(h << 7) + (w0 >> 2)] = outw;
    if (changed) g_flags[iter] = 1;   // benign race
}

// ---------------------------------------------------------------------------
// Kernel 3: warp-per-column capped vertical distance -> g2 = d^2.
// d(h) = min(h - last_set<=h, next_set>=h - h, 1024)  (== reference scans).
// ---------------------------------------------------------------------------
__global__ void k_vscan()
{
    int gw   = (blockIdx.x * blockDim.x + threadIdx.x) >> 5;  // 0..2047
    int lane = threadIdx.x & 31;
    int b = gw >> 9;
    int w = gw & (W - 1);
    const unsigned char* __restrict__ im = g_imgA + (size_t)b * HW;
    float* __restrict__ g2 = g_g2 + (size_t)b * HW;

    int base_row = lane * 16;
    unsigned char v[16];
    #pragma unroll
    for (int k = 0; k < 16; k++) v[k] = im[(base_row + k) * W + w];

    // last set row index within chunk (ascending)
    int ll = -100000;
    #pragma unroll
    for (int k = 0; k < 16; k++) if (v[k]) ll = base_row + k;
    int incl = ll;
    #pragma unroll
    for (int o = 1; o < 32; o <<= 1) {
        int x = __shfl_up_sync(0xffffffffu, incl, o);
        if (lane >= o) incl = max(incl, x);
    }
    int prefix = __shfl_up_sync(0xffffffffu, incl, 1);
    if (lane == 0) prefix = -100000;

    // first set row index within chunk (for "next")
    int lf = 100000;
    #pragma unroll
    for (int k = 15; k >= 0; k--) if (v[k]) lf = base_row + k;
    int incl2 = lf;
    #pragma unroll
    for (int o = 1; o < 32; o <<= 1) {
        int x = __shfl_down_sync(0xffffffffu, incl2, o);
        if (lane < 32 - o) incl2 = min(incl2, x);
    }
    int suffix = __shfl_down_sync(0xffffffffu, incl2, 1);
    if (lane == 31) suffix = 100000;

    int nxt[16];
    int cur = suffix;
    #pragma unroll
    for (int k = 15; k >= 0; k--) {
        int idx = base_row + k;
        if (v[k]) cur = idx;
        nxt[k] = cur;
    }
    int last = prefix;
    #pragma unroll
    for (int k = 0; k < 16; k++) {
        int idx = base_row + k;
        if (v[k]) last = idx;
        float fd = fminf((float)(idx - last), 1024.0f);
        float bd = fminf((float)(nxt[k] - idx), 1024.0f);
        float d  = fminf(fd, bd);
        g2[idx * W + w] = d * d;
    }
}

// ---------------------------------------------------------------------------
// Kernel 4: exact row EDT via expanding search (terminates when r^2 >= d).
// All arithmetic on exact small integers -> bit-identical to brute force.
// ---------------------------------------------------------------------------
__global__ void k_edt()
{
    __shared__ float sg[W];
    int row = blockIdx.x;                  // b*H + h
    const float* __restrict__ g2row = g_g2 + (size_t)row * W;
    int w = threadIdx.x;
    sg[w] = g2row[w];
    __syncthreads();

    float d = sg[w];
    for (int r = 1; r < W; r++) {
        float rr = (float)(r * r);
        if (rr >= d) break;
        int ql = w - r, qr = w + r;
        if (ql >= 0) d = fminf(d, sg[ql] + rr);
        if (qr < W)  d = fminf(d, sg[qr] + rr);
    }
    g_wexp[(size_t)row * W + w] = expf(sqrtf(d) * -0.05f);   // exp(-dist/20)
}

// ---------------------------------------------------------------------------
// Kernel 5: fused endpoints + broadcast-correct base + direction convs.
// base = (1/(B^2*HW)) * sum_{h,w} (sum_b Wmap[b,h,w]) * (sum_b L[b,h,w])
// Exactly HW/4 = 65536 threads: one per (h, 4-pixel group).
// ---------------------------------------------------------------------------
__global__ void k_reduce()
{
    int t  = blockIdx.x * blockDim.x + threadIdx.x;   // 0..65535
    int h  = t >> 7;                                   // 0..511
    int w0 = (t & 127) << 2;

    double sc = 0.0, sd = 0.0;
    float sumW[4] = {0,0,0,0}, sumL[4] = {0,0,0,0};

    #pragma unroll
    for (int b = 0; b < BB; b++) {
        const unsigned char* im = g_imgA + (size_t)b * HW;
        u64 wa = winrow(im, h - 1, w0);
        u64 wc = winrow(im, h,     w0);
        u64 wb = winrow(im, h + 1, w0);
        float4 we = *(const float4*)(g_wexp + (size_t)b * HW + h * W + w0);
        float4 Lv = *(const float4*)(g_L    + (size_t)b * HW + h * W + w0);
        float wex[4] = {we.x, we.y, we.z, we.w};
        float Lx[4]  = {Lv.x, Lv.y, Lv.z, Lv.w};

        #pragma unroll
        for (int j = 0; j < 4; j++) {
            int sh = (j + 1) * 8;
            int s  = (int)((wc >> sh) & 1);
            int P8 = (int)((wc >> (sh - 8)) & 1), P4 = (int)((wc >> (sh + 8)) & 1);
            int P9 = (int)((wa >> (sh - 8)) & 1), P2 = (int)((wa >> sh) & 1), P3 = (int)((wa >> (sh + 8)) & 1);
            int P7 = (int)((wb >> (sh - 8)) & 1), P6 = (int)((wb >> sh) & 1), P5 = (int)((wb >> (sh + 8)) & 1);

            int cnt = P2 + P3 + P4 + P5 + P6 + P7 + P8 + P9;
            float e = (s && (cnt == 1 || cnt >= 3)) ? 20.0f : 0.0f;
            sumW[j] += wex[j] + e;
            sumL[j] += Lx[j];

            float fs  = (float)s;
            float rh  = (float)(P8 + s + P4);
            float rv  = (float)(P2 + s + P6);
            float rd1 = (float)(P9 + s + P5);
            float rd2 = (float)(P3 + s + P7);
            sc += (double)(fabsf(rh - fs) + fabsf(rv - fs) + fabsf(rd1 - fs) + fabsf(rd2 - fs));
            sd += (double)(fabsf(1.0f - rh) + fabsf(1.0f - rv) + fabsf(1.0f - rd1) + fabsf(1.0f - rd2));
        }
    }
    double sb = 0.0;
    #pragma unroll
    for (int j = 0; j < 4; j++) sb += (double)sumW[j] * (double)sumL[j];

    __shared__ double sh0[RED_THREADS], sh1[RED_THREADS], sh2[RED_THREADS];
    int tt = threadIdx.x;
    sh0[tt] = sb; sh1[tt] = sc; sh2[tt] = sd;
    __syncthreads();
    for (int s2 = RED_THREADS / 2; s2 > 0; s2 >>= 1) {
        if (tt < s2) {
            sh0[tt] += sh0[tt + s2];
            sh1[tt] += sh1[tt + s2];
            sh2[tt] += sh2[tt + s2];
        }
        __syncthreads();
    }
    if (tt == 0) {
        g_part[blockIdx.x]                  = sh0[0];
        g_part[RED_BLOCKS + blockIdx.x]     = sh1[0];
        g_part[2 * RED_BLOCKS + blockIdx.x] = sh2[0];
    }
}

// ---------------------------------------------------------------------------
// Kernel 6: deterministic final sum -> scalar loss
// ---------------------------------------------------------------------------
__global__ void k_final(float* __restrict__ out)
{
    __shared__ double sh0[RED_THREADS], sh1[RED_THREADS], sh2[RED_THREADS];
    int t = threadIdx.x;
    double a = 0.0, b = 0.0, c = 0.0;
    for (int i = t; i < RED_BLOCKS; i += RED_THREADS) {
        a += g_part[i];
        b += g_part[RED_BLOCKS + i];
        c += g_part[2 * RED_BLOCKS + i];
    }
    sh0[t] = a; sh1[t] = b; sh2[t] = c;
    __syncthreads();
    for (int s2 = RED_THREADS / 2; s2 > 0; s2 >>= 1) {
        if (t < s2) {
            sh0[t] += sh0[t + s2];
            sh1[t] += sh1[t + s2];
            sh2[t] += sh2[t + s2];
        }
        __syncthreads();
    }
    if (t == 0) {
        double base = sh0[0] / (double)((double)BB * BB * HW);   // 16*HW
        double cont = sh1[0] / (double)NPIX;
        double dirl = sh2[0] / (double)NPIX;
        out[0] = (float)(base + 0.3 * cont + 0.5 * dirl);
    }
}

// ---------------------------------------------------------------------------
extern "C" void kernel_launch(void* const* d_in, const int* in_sizes, int n_in,
                              void* d_out, int out_size)
{
    const float* pred   = (const float*)d_in[0];
    const int*   target = (const int*)d_in[1];

    k_prep<<<1024, 256>>>(pred, target);

    for (int it = 0; it < NITER; ++it) {
        k_thin<true ><<<1024, 256>>>(it);   // substep 1: A -> B
        k_thin<false><<<1024, 256>>>(it);   // substep 2: B -> A
    }

    k_vscan<<<256, 256>>>();                 // 2048 warps, warp-per-column
    k_edt<<<BB * H, W>>>();
    k_reduce<<<RED_BLOCKS, RED_THREADS>>>(); // 65536 threads exactly
    k_final<<<1, RED_THREADS>>>((float*)d_out);
}

// round 4
// speedup vs baseline: 4.5407x; 1.1952x over previous
#include <cuda_runtime.h>
#include <math.h>

// Problem constants
#define BB 4
#define H 512
#define W 512
#define HW (H*W)          // 262144 = 2^18
#define NPIX (BB*HW)      // 1048576
#define NITER 16          // max Zhang-Suen double-steps (early-exit when converged)
#define RED_BLOCKS 256    // k_reduce: 256 blocks * 256 threads = HW/4 groups exactly
#define RED_THREADS 256

typedef unsigned long long u64;
typedef unsigned int u32;

// Static device scratch (no allocation allowed). Aligned for u64 loads.
__device__ __align__(128) unsigned char g_imgA[NPIX];
__device__ __align__(128) unsigned char g_imgB[NPIX];
__device__ float  g_L[NPIX];      // per-pixel CE loss
__device__ float  g_g2[NPIX];     // vertical capped distance squared
__device__ float  g_wexp[NPIX];   // exp(-dist/K)
__device__ int    g_flags[NITER];
__device__ double g_part[3*RED_BLOCKS];

// ---------------------------------------------------------------------------
// Kernel 1: log-softmax CE loss + argmax image, zero the change flags
// ---------------------------------------------------------------------------
__global__ void k_prep(const float* __restrict__ pred, const int* __restrict__ target)
{
    int tid0 = blockIdx.x * blockDim.x + threadIdx.x;
    if (tid0 < NITER) g_flags[tid0] = 0;
    int stride = gridDim.x * blockDim.x;
    for (int i = tid0; i < NPIX; i += stride) {
        int b  = i >> 18;
        int hw = i & (HW - 1);
        float p0 = pred[((size_t)b * 2    ) * HW + hw];
        float p1 = pred[((size_t)b * 2 + 1) * HW + hw];
        float m   = fmaxf(p0, p1);
        float lse = m + logf(expf(p0 - m) + expf(p1 - m));
        int   t   = target[i];
        g_L[i]    = lse - (t ? p1 : p0);
        g_imgA[i] = (p1 > p0) ? (unsigned char)1 : (unsigned char)0;
    }
}

// ---------------------------------------------------------------------------
// SWAR helpers. Pixels are 0/1 bytes; u64 = 8 lanes, little-endian byte j is
// pixel w0+j. "w" = west-shifted window (byte j holds pixel w0+j-1),
// "e" = east-shifted (byte j holds pixel w0+j+1). OOB -> 0.
// ---------------------------------------------------------------------------
#define ONES8 0x0101010101010101ULL
#define HI8   0x8080808080808080ULL

struct Row3 { u64 c, w, e; };

__device__ __forceinline__ Row3 ldrow(const unsigned char* __restrict__ im, int r, int gx)
{
    Row3 R;
    if (r < 0 || r >= H) { R.c = R.w = R.e = 0ULL; return R; }
    const u64* p = (const u64*)(im + r * W);
    u64 c  = p[gx];
    u64 lb = (gx > 0)  ? (u64)im[r * W + gx * 8 - 1] : 0ULL;
    u64 rb = (gx < 63) ? (u64)im[r * W + gx * 8 + 8] : 0ULL;
    R.c = c;
    R.w = (c << 8) | lb;
    R.e = (c >> 8) | (rb << 56);
    return R;
}

// high-bit-per-byte mask of (byte >= cst), valid for byte values <= 0x7f
__device__ __forceinline__ u64 swar_ge(u64 x, u64 cstTimesOnes)
{
    return ((x | HI8) - cstTimesOnes) & HI8;
}

// ---------------------------------------------------------------------------
// Kernel 2: one Zhang-Suen sub-step, 8 pixels per thread (byte SWAR).
// ---------------------------------------------------------------------------
template<bool FIRST>
__global__ void k_thin(int iter)
{
    if (iter > 0 && g_flags[iter - 1] == 0) return;
    const unsigned char* __restrict__ src = FIRST ? g_imgA : g_imgB;
    unsigned char* __restrict__ dst       = FIRST ? g_imgB : g_imgA;

    int t  = blockIdx.x * blockDim.x + threadIdx.x;   // 0..131071 (NPIX/8)
    int b  = t >> 15;                                  // 32768 u64-groups / image
    int g  = t & 32767;
    int h  = g >> 6;                                   // 64 u64-groups per row
    int gx = g & 63;
    const unsigned char* im = src + (size_t)b * HW;

    Row3 A = ldrow(im, h - 1, gx);   // row above
    Row3 C = ldrow(im, h,     gx);   // center row
    Row3 Bl= ldrow(im, h + 1, gx);   // row below

    u64 P2 = A.c,  P3 = A.e,  P4 = C.e,  P5 = Bl.e;
    u64 P6 = Bl.c, P7 = Bl.w, P8 = C.w,  P9 = A.w;

    // neighbor count per byte (max 8, carry-free)
    u64 bs = P2 + P3 + P4 + P5 + P6 + P7 + P8 + P9;

    // 0->1 transitions around the ring
    u64 a = ((P2 ^ ONES8) & P3) + ((P3 ^ ONES8) & P4)
          + ((P4 ^ ONES8) & P5) + ((P5 ^ ONES8) & P6)
          + ((P6 ^ ONES8) & P7) + ((P7 ^ ONES8) & P8)
          + ((P8 ^ ONES8) & P9) + ((P9 ^ ONES8) & P2);

    u64 c1, c2;
    if (FIRST) { c1 = (P2 & P4 & P6) ^ ONES8; c2 = (P4 & P6 & P8) ^ ONES8; }
    else       { c1 = (P2 & P4 & P8) ^ ONES8; c2 = (P2 & P6 & P8) ^ ONES8; }
    u64 cc = c1 & c2;                         // byte 1 where both products zero

    u64 ge2  = swar_ge(bs, 2 * ONES8);
    u64 le6  = swar_ge(bs, 7 * ONES8) ^ HI8;
    u64 aeq1 = swar_ge(a, ONES8) & (swar_ge(a, 2 * ONES8) ^ HI8);

    u64 pH = (C.c << 7) & HI8;
    u64 cH = (cc  << 7) & HI8;

    u64 rem = pH & ge2 & le6 & aeq1 & cH;     // high bit per removed byte
    u64 out = C.c & ~(rem >> 7);

    ((u64*)(dst + (size_t)b * HW))[(h << 6) + gx] = out;
    if (rem) g_flags[iter] = 1;               // benign race
}

// ---------------------------------------------------------------------------
// 48-bit row window for k_reduce (4 px/thread): byte for pixel w0+j at bit
// (j+1)*8; bit 0 byte is pixel w0-1; bit 40 byte is pixel w0+4. OOB -> 0.
// ---------------------------------------------------------------------------
__device__ __forceinline__ u64 winrow(const unsigned char* __restrict__ im, int r, int w0)
{
    if (r < 0 || r >= H) return 0ULL;
    const u32* imu = (const u32*)(im + r * W);
    int c = w0 >> 2;
    u32 C  = imu[c];
    u32 Lw = (w0 > 0)     ? imu[c - 1] : 0u;
    u32 Rw = (w0 + 4 < W) ? imu[c + 1] : 0u;
    return (u64)(Lw >> 24) | ((u64)C << 8) | ((u64)(Rw & 0xFFu) << 40);
}

// ---------------------------------------------------------------------------
// Kernel 3: warp-per-column capped vertical distance -> g2 = d^2.
// ---------------------------------------------------------------------------
__global__ void k_vscan()
{
    int gw   = (blockIdx.x * blockDim.x + threadIdx.x) >> 5;  // 0..2047
    int lane = threadIdx.x & 31;
    int b = gw >> 9;
    int w = gw & (W - 1);
    const unsigned char* __restrict__ im = g_imgA + (size_t)b * HW;
    float* __restrict__ g2 = g_g2 + (size_t)b * HW;

    int base_row = lane * 16;
    unsigned char v[16];
    #pragma unroll
    for (int k = 0; k < 16; k++) v[k] = im[(base_row + k) * W + w];

    int ll = -100000;
    #pragma unroll
    for (int k = 0; k < 16; k++) if (v[k]) ll = base_row + k;
    int incl = ll;
    #pragma unroll
    for (int o = 1; o < 32; o <<= 1) {
        int x = __shfl_up_sync(0xffffffffu, incl, o);
        if (lane >= o) incl = max(incl, x);
    }
    int prefix = __shfl_up_sync(0xffffffffu, incl, 1);
    if (lane == 0) prefix = -100000;

    int lf = 100000;
    #pragma unroll
    for (int k = 15; k >= 0; k--) if (v[k]) lf = base_row + k;
    int incl2 = lf;
    #pragma unroll
    for (int o = 1; o < 32; o <<= 1) {
        int x = __shfl_down_sync(0xffffffffu, incl2, o);
        if (lane < 32 - o) incl2 = min(incl2, x);
    }
    int suffix = __shfl_down_sync(0xffffffffu, incl2, 1);
    if (lane == 31) suffix = 100000;

    int nxt[16];
    int cur = suffix;
    #pragma unroll
    for (int k = 15; k >= 0; k--) {
        int idx = base_row + k;
        if (v[k]) cur = idx;
        nxt[k] = cur;
    }
    int last = prefix;
    #pragma unroll
    for (int k = 0; k < 16; k++) {
        int idx = base_row + k;
        if (v[k]) last = idx;
        float fd = fminf((float)(idx - last), 1024.0f);
        float bd = fminf((float)(nxt[k] - idx), 1024.0f);
        float d  = fminf(fd, bd);
        g2[idx * W + w] = d * d;
    }
}

// ---------------------------------------------------------------------------
// Kernel 4: exact row EDT via expanding search (terminates when r^2 >= d).
// ---------------------------------------------------------------------------
__global__ void k_edt()
{
    __shared__ float sg[W];
    int row = blockIdx.x;                  // b*H + h
    const float* __restrict__ g2row = g_g2 + (size_t)row * W;
    int w = threadIdx.x;
    sg[w] = g2row[w];
    __syncthreads();

    float d = sg[w];
    for (int r = 1; r < W; r++) {
        float rr = (float)(r * r);
        if (rr >= d) break;
        int ql = w - r, qr = w + r;
        if (ql >= 0) d = fminf(d, sg[ql] + rr);
        if (qr < W)  d = fminf(d, sg[qr] + rr);
    }
    g_wexp[(size_t)row * W + w] = expf(sqrtf(d) * -0.05f);   // exp(-dist/20)
}

// ---------------------------------------------------------------------------
// Kernel 5: fused endpoints + broadcast-correct base + direction convs.
// base = (1/(B^2*HW)) * sum_{h,w} (sum_b Wmap[b,h,w]) * (sum_b L[b,h,w])
// Exactly HW/4 = 65536 threads: one per (h, 4-pixel group).
// ---------------------------------------------------------------------------
__global__ void k_reduce()
{
    int t  = blockIdx.x * blockDim.x + threadIdx.x;   // 0..65535
    int h  = t >> 7;                                   // 0..511
    int w0 = (t & 127) << 2;

    double sc = 0.0, sd = 0.0;
    float sumW[4] = {0,0,0,0}, sumL[4] = {0,0,0,0};

    #pragma unroll
    for (int b = 0; b < BB; b++) {
        const unsigned char* im = g_imgA + (size_t)b * HW;
        u64 wa = winrow(im, h - 1, w0);
        u64 wc = winrow(im, h,     w0);
        u64 wb = winrow(im, h + 1, w0);
        float4 we = *(const float4*)(g_wexp + (size_t)b * HW + h * W + w0);
        float4 Lv = *(const float4*)(g_L    + (size_t)b * HW + h * W + w0);
        float wex[4] = {we.x, we.y, we.z, we.w};
        float Lx[4]  = {Lv.x, Lv.y, Lv.z, Lv.w};

        #pragma unroll
        for (int j = 0; j < 4; j++) {
            int sh = (j + 1) * 8;
            int s  = (int)((wc >> sh) & 1);
            int P8 = (int)((wc >> (sh - 8)) & 1), P4 = (int)((wc >> (sh + 8)) & 1);
            int P9 = (int)((wa >> (sh - 8)) & 1), P2 = (int)((wa >> sh) & 1), P3 = (int)((wa >> (sh + 8)) & 1);
            int P7 = (int)((wb >> (sh - 8)) & 1), P6 = (int)((wb >> sh) & 1), P5 = (int)((wb >> (sh + 8)) & 1);

            int cnt = P2 + P3 + P4 + P5 + P6 + P7 + P8 + P9;
            float e = (s && (cnt == 1 || cnt >= 3)) ? 20.0f : 0.0f;
            sumW[j] += wex[j] + e;
            sumL[j] += Lx[j];

            float fs  = (float)s;
            float rh  = (float)(P8 + s + P4);
            float rv  = (float)(P2 + s + P6);
            float rd1 = (float)(P9 + s + P5);
            float rd2 = (float)(P3 + s + P7);
            sc += (double)(fabsf(rh - fs) + fabsf(rv - fs) + fabsf(rd1 - fs) + fabsf(rd2 - fs));
            sd += (double)(fabsf(1.0f - rh) + fabsf(1.0f - rv) + fabsf(1.0f - rd1) + fabsf(1.0f - rd2));
        }
    }
    double sb = 0.0;
    #pragma unroll
    for (int j = 0; j < 4; j++) sb += (double)sumW[j] * (double)sumL[j];

    __shared__ double sh0[RED_THREADS], sh1[RED_THREADS], sh2[RED_THREADS];
    int tt = threadIdx.x;
    sh0[tt] = sb; sh1[tt] = sc; sh2[tt] = sd;
    __syncthreads();
    for (int s2 = RED_THREADS / 2; s2 > 0; s2 >>= 1) {
        if (tt < s2) {
            sh0[tt] += sh0[tt + s2];
            sh1[tt] += sh1[tt + s2];
            sh2[tt] += sh2[tt + s2];
        }
        __syncthreads();
    }
    if (tt == 0) {
        g_part[blockIdx.x]                  = sh0[0];
        g_part[RED_BLOCKS + blockIdx.x]     = sh1[0];
        g_part[2 * RED_BLOCKS + blockIdx.x] = sh2[0];
    }
}

// ---------------------------------------------------------------------------
// Kernel 6: deterministic final sum -> scalar loss
// ---------------------------------------------------------------------------
__global__ void k_final(float* __restrict__ out)
{
    __shared__ double sh0[RED_THREADS], sh1[RED_THREADS], sh2[RED_THREADS];
    int t = threadIdx.x;
    double a = 0.0, b = 0.0, c = 0.0;
    for (int i = t; i < RED_BLOCKS; i += RED_THREADS) {
        a += g_part[i];
        b += g_part[RED_BLOCKS + i];
        c += g_part[2 * RED_BLOCKS + i];
    }
    sh0[t] = a; sh1[t] = b; sh2[t] = c;
    __syncthreads();
    for (int s2 = RED_THREADS / 2; s2 > 0; s2 >>= 1) {
        if (t < s2) {
            sh0[t] += sh0[t + s2];
            sh1[t] += sh1[t + s2];
            sh2[t] += sh2[t + s2];
        }
        __syncthreads();
    }
    if (t == 0) {
        double base = sh0[0] / (double)((double)BB * BB * HW);   // 16*HW
        double cont = sh1[0] / (double)NPIX;
        double dirl = sh2[0] / (double)NPIX;
        out[0] = (float)(base + 0.3 * cont + 0.5 * dirl);
    }
}

// ---------------------------------------------------------------------------
extern "C" void kernel_launch(void* const* d_in, const int* in_sizes, int n_in,
                              void* d_out, int out_size)
{
    const float* pred   = (const float*)d_in[0];
    const int*   target = (const int*)d_in[1];

    k_prep<<<1024, 256>>>(pred, target);

    for (int it = 0; it < NITER; ++it) {
        k_thin<true ><<<512, 256>>>(it);   // substep 1: A -> B  (8 px/thread)
        k_thin<false><<<512, 256>>>(it);   // substep 2: B -> A
    }

    k_vscan<<<256, 256>>>();                 // 2048 warps, warp-per-column
    k_edt<<<BB * H, W>>>();
    k_reduce<<<RED_BLOCKS, RED_THREADS>>>(); // 65536 threads exactly
    k_final<<<1, RED_THREADS>>>((float*)d_out);
}

// round 5
// speedup vs baseline: 6.3519x; 1.3989x over previous
#include <cuda_runtime.h>
#include <math.h>

// Problem constants
#define BB 4
#define H 512
#define W 512
#define HW (H*W)          // 262144
#define NPIX (BB*HW)      // 1048576
#define NSUB 32           // 32 substeps = 16 Zhang-Suen double-steps (verified enough)
#define RED_BLOCKS 256
#define RED_THREADS 256

typedef unsigned long long u64;
typedef unsigned int u32;

#define ONES8 0x0101010101010101ULL
#define HI8   0x8080808080808080ULL
#define BITM  0x8040201008040201ULL

// Static device scratch
__device__ __align__(128) u64 g_bits[BB * H * 8];     // 1 bit/pixel bitboards
__device__ __align__(128) unsigned char g_imgA[NPIX]; // final skeleton as bytes
__device__ float  g_L[NPIX];
__device__ float  g_g2[NPIX];
__device__ float  g_wexp[NPIX];
__device__ double g_part[3*RED_BLOCKS];

// ---------------------------------------------------------------------------
// Kernel 1: log-softmax CE loss + packed argmax bitboard. 8 px/thread.
// ---------------------------------------------------------------------------
__global__ void k_prep(const float* __restrict__ pred, const int* __restrict__ target)
{
    int t = blockIdx.x * blockDim.x + threadIdx.x;    // 0..131071
    int b = t >> 15;
    int q = t & 32767;                                 // 8-pixel group in image
    int i0 = q << 3;

    const float4* p0v = (const float4*)(pred + (size_t)b * 2 * HW + i0);
    const float4* p1v = (const float4*)(pred + (size_t)b * 2 * HW + HW + i0);
    const int4*   tgv = (const int4*)(target + (size_t)b * HW + i0);
    float4 a0 = p0v[0], a1 = p0v[1];
    float4 b0 = p1v[0], b1 = p1v[1];
    int4   t0 = tgv[0], t1 = tgv[1];

    float p0a[8] = {a0.x,a0.y,a0.z,a0.w, a1.x,a1.y,a1.z,a1.w};
    float p1a[8] = {b0.x,b0.y,b0.z,b0.w, b1.x,b1.y,b1.z,b1.w};
    int   tg[8]  = {t0.x,t0.y,t0.z,t0.w, t1.x,t1.y,t1.z,t1.w};

    float Lo[8];
    u32 bits = 0;
    #pragma unroll
    for (int j = 0; j < 8; j++) {
        float p0 = p0a[j], p1 = p1a[j];
        float m   = fmaxf(p0, p1);
        float lse = m + logf(expf(p0 - m) + expf(p1 - m));
        Lo[j] = lse - (tg[j] ? p1 : p0);
        bits |= (p1 > p0 ? 1u : 0u) << j;
    }
    float4* Lv = (float4*)(g_L + (size_t)b * HW + i0);
    Lv[0] = make_float4(Lo[0], Lo[1], Lo[2], Lo[3]);
    Lv[1] = make_float4(Lo[4], Lo[5], Lo[6], Lo[7]);
    ((unsigned char*)g_bits)[(size_t)b * 32768 + q] = (unsigned char)bits;
}

// ---------------------------------------------------------------------------
// Kernel 2: ALL thinning in one launch. 32 blocks = 4 images x 8 bands of 64
// rows; 32-row halo each side; one halo row consumed per substep. Bitboard
// Zhang-Suen via CSA adder tree. Final band unpacked to byte image.
// ---------------------------------------------------------------------------
__global__ void __launch_bounds__(512, 1) k_thin_all()
{
    __shared__ u64 buf0[128 * 8];
    __shared__ u64 buf1[128 * 8];

    int img  = blockIdx.x >> 3;
    int band = blockIdx.x & 7;
    int t    = threadIdx.x;
    const u64* gb = g_bits + (size_t)img * 4096;

    // load 128 tile rows (image rows band*64-32 .. +96), OOB -> 0
    for (int i = t; i < 1024; i += 512) {
        int r   = i >> 3;
        int wx  = i & 7;
        int imr = band * 64 - 32 + r;
        buf0[i] = (imr >= 0 && imr < H) ? gb[imr * 8 + wx] : 0ULL;
    }
    __syncthreads();

    #pragma unroll 1
    for (int s = 0; s < NSUB; s++) {
        const u64* __restrict__ src = (s & 1) ? buf1 : buf0;
        u64* __restrict__ dst       = (s & 1) ? buf0 : buf1;
        bool FIRST = ((s & 1) == 0);
        int lo = s + 1, hi = 126 - s;
        int n  = (hi - lo + 1) * 8;

        for (int i = t; i < n; i += 512) {
            int r  = lo + (i >> 3);
            int wx = i & 7;
            int base = r * 8;

            u64 ctr = src[base + wx];
            u64 cW = wx      ? src[base + wx - 1] : 0ULL;
            u64 cE = wx < 7  ? src[base + wx + 1] : 0ULL;
            u64 up = src[base - 8 + wx];
            u64 uW = wx      ? src[base - 8 + wx - 1] : 0ULL;
            u64 uE = wx < 7  ? src[base - 8 + wx + 1] : 0ULL;
            u64 dn = src[base + 8 + wx];
            u64 dW = wx      ? src[base + 8 + wx - 1] : 0ULL;
            u64 dE = wx < 7  ? src[base + 8 + wx + 1] : 0ULL;

            u64 P2 = up, P6 = dn;
            u64 P4 = (ctr >> 1) | (cE << 63);
            u64 P8 = (ctr << 1) | (cW >> 63);
            u64 P3 = (up  >> 1) | (uE << 63);
            u64 P9 = (up  << 1) | (uW >> 63);
            u64 P5 = (dn  >> 1) | (dE << 63);
            u64 P7 = (dn  << 1) | (dW >> 63);

            // bit-sliced neighbor count (CSA tree), value 0..8 in s0..s3
            u64 x, y;
            x = P2 ^ P3;            u64 s1a = x ^ P4;  u64 c1a = (P2 & P3) | (P4 & x);
            x = P5 ^ P6;            u64 s1b = x ^ P7;  u64 c1b = (P5 & P6) | (P7 & x);
            x = s1a ^ s1b;          u64 s1c = x ^ P8;  u64 c1c = (s1a & s1b) | (P8 & x);
            u64 s0  = s1c ^ P9;     u64 c1d = s1c & P9;
            y = c1a ^ c1b;          u64 s2a = y ^ c1c; u64 c2a = (c1a & c1b) | (c1c & y);
            u64 sl1 = s2a ^ c1d;    u64 c2b = s2a & c1d;
            u64 sl2 = c2a ^ c2b;    u64 sl3 = c2a & c2b;

            u64 ge2 = sl1 | sl2 | sl3;
            u64 ge7 = sl3 | (sl2 & sl1 & s0);
            u64 in24 = ge2 & ~ge7;

            // exactly-one 0->1 transition around the ring
            u64 t1 = ~P2 & P3, t2 = ~P3 & P4, t3 = ~P4 & P5, t4 = ~P5 & P6;
            u64 t5 = ~P6 & P7, t6 = ~P7 & P8, t7 = ~P8 & P9, t8 = ~P9 & P2;
            u64 acc = t1, multi = 0ULL;
            multi |= acc & t2; acc |= t2;
            multi |= acc & t3; acc |= t3;
            multi |= acc & t4; acc |= t4;
            multi |= acc & t5; acc |= t5;
            multi |= acc & t6; acc |= t6;
            multi |= acc & t7; acc |= t7;
            multi |= acc & t8; acc |= t8;
            u64 eq1 = acc & ~multi;

            u64 cc;
            if (FIRST) cc = ~(P2 & P4 & P6) & ~(P4 & P6 & P8);
            else       cc = ~(P2 & P4 & P8) & ~(P2 & P6 & P8);

            u64 rem = ctr & in24 & eq1 & cc;
            dst[base + wx] = ctr ^ rem;
        }
        __syncthreads();
    }

    // unpack band rows [32,96) of buf0 (NSUB even -> final state in buf0)
    {
        int i  = t;                       // 512 words exactly
        int r  = 32 + (i >> 3);
        int wx = i & 7;
        u64 v  = buf0[r * 8 + wx];
        int imr = band * 64 + (i >> 3);
        u64* outp = (u64*)(g_imgA + (size_t)img * HW + imr * W + wx * 64);
        #pragma unroll
        for (int k = 0; k < 8; k++) {
            u64 bb = (v >> (k * 8)) & 0xFFULL;
            u64 e  = ((((bb * ONES8) & BITM) + 0x7F7F7F7F7F7F7F7FULL) & HI8) >> 7;
            outp[k] = e;
        }
    }
}

// ---------------------------------------------------------------------------
// Kernel 3: warp-per-column capped vertical distance -> g2 = d^2.
// ---------------------------------------------------------------------------
__global__ void k_vscan()
{
    int gw   = (blockIdx.x * blockDim.x + threadIdx.x) >> 5;  // 0..2047
    int lane = threadIdx.x & 31;
    int b = gw >> 9;
    int w = gw & (W - 1);
    const unsigned char* __restrict__ im = g_imgA + (size_t)b * HW;
    float* __restrict__ g2 = g_g2 + (size_t)b * HW;

    int base_row = lane * 16;
    unsigned char v[16];
    #pragma unroll
    for (int k = 0; k < 16; k++) v[k] = im[(base_row + k) * W + w];

    int ll = -100000;
    #pragma unroll
    for (int k = 0; k < 16; k++) if (v[k]) ll = base_row + k;
    int incl = ll;
    #pragma unroll
    for (int o = 1; o < 32; o <<= 1) {
        int x = __shfl_up_sync(0xffffffffu, incl, o);
        if (lane >= o) incl = max(incl, x);
    }
    int prefix = __shfl_up_sync(0xffffffffu, incl, 1);
    if (lane == 0) prefix = -100000;

    int lf = 100000;
    #pragma unroll
    for (int k = 15; k >= 0; k--) if (v[k]) lf = base_row + k;
    int incl2 = lf;
    #pragma unroll
    for (int o = 1; o < 32; o <<= 1) {
        int x = __shfl_down_sync(0xffffffffu, incl2, o);
        if (lane < 32 - o) incl2 = min(incl2, x);
    }
    int suffix = __shfl_down_sync(0xffffffffu, incl2, 1);
    if (lane == 31) suffix = 100000;

    int nxt[16];
    int cur = suffix;
    #pragma unroll
    for (int k = 15; k >= 0; k--) {
        int idx = base_row + k;
        if (v[k]) cur = idx;
        nxt[k] = cur;
    }
    int last = prefix;
    #pragma unroll
    for (int k = 0; k < 16; k++) {
        int idx = base_row + k;
        if (v[k]) last = idx;
        float fd = fminf((float)(idx - last), 1024.0f);
        float bd = fminf((float)(nxt[k] - idx), 1024.0f);
        float d  = fminf(fd, bd);
        g2[idx * W + w] = d * d;
    }
}

// ---------------------------------------------------------------------------
// Kernel 4: exact row EDT via expanding search.
// ---------------------------------------------------------------------------
__global__ void k_edt()
{
    __shared__ float sg[W];
    int row = blockIdx.x;
    const float* __restrict__ g2row = g_g2 + (size_t)row * W;
    int w = threadIdx.x;
    sg[w] = g2row[w];
    __syncthreads();

    float d = sg[w];
    for (int r = 1; r < W; r++) {
        float rr = (float)(r * r);
        if (rr >= d) break;
        int ql = w - r, qr = w + r;
        if (ql >= 0) d = fminf(d, sg[ql] + rr);
        if (qr < W)  d = fminf(d, sg[qr] + rr);
    }
    g_wexp[(size_t)row * W + w] = expf(sqrtf(d) * -0.05f);
}

// ---------------------------------------------------------------------------
// 48-bit row window for k_reduce (4 px/thread)
// ---------------------------------------------------------------------------
__device__ __forceinline__ u64 winrow(const unsigned char* __restrict__ im, int r, int w0)
{
    if (r < 0 || r >= H) return 0ULL;
    const u32* imu = (const u32*)(im + r * W);
    int c = w0 >> 2;
    u32 C  = imu[c];
    u32 Lw = (w0 > 0)     ? imu[c - 1] : 0u;
    u32 Rw = (w0 + 4 < W) ? imu[c + 1] : 0u;
    return (u64)(Lw >> 24) | ((u64)C << 8) | ((u64)(Rw & 0xFFu) << 40);
}

// ---------------------------------------------------------------------------
// Kernel 5: fused endpoints + broadcast-correct base + direction convs.
// ---------------------------------------------------------------------------
__global__ void k_reduce()
{
    int t  = blockIdx.x * blockDim.x + threadIdx.x;   // 0..65535
    int h  = t >> 7;
    int w0 = (t & 127) << 2;

    double sc = 0.0, sd = 0.0;
    float sumW[4] = {0,0,0,0}, sumL[4] = {0,0,0,0};

    #pragma unroll
    for (int b = 0; b < BB; b++) {
        const unsigned char* im = g_imgA + (size_t)b * HW;
        u64 wa = winrow(im, h - 1, w0);
        u64 wc = winrow(im, h,     w0);
        u64 wb = winrow(im, h + 1, w0);
        float4 we = *(const float4*)(g_wexp + (size_t)b * HW + h * W + w0);
        float4 Lv = *(const float4*)(g_L    + (size_t)b * HW + h * W + w0);
        float wex[4] = {we.x, we.y, we.z, we.w};
        float Lx[4]  = {Lv.x, Lv.y, Lv.z, Lv.w};

        #pragma unroll
        for (int j = 0; j < 4; j++) {
            int sh = (j + 1) * 8;
            int s  = (int)((wc >> sh) & 1);
            int P8 = (int)((wc >> (sh - 8)) & 1), P4 = (int)((wc >> (sh + 8)) & 1);
            int P9 = (int)((wa >> (sh - 8)) & 1), P2 = (int)((wa >> sh) & 1), P3 = (int)((wa >> (sh + 8)) & 1);
            int P7 = (int)((wb >> (sh - 8)) & 1), P6 = (int)((wb >> sh) & 1), P5 = (int)((wb >> (sh + 8)) & 1);

            int cnt = P2 + P3 + P4 + P5 + P6 + P7 + P8 + P9;
            float e = (s && (cnt == 1 || cnt >= 3)) ? 20.0f : 0.0f;
            sumW[j] += wex[j] + e;
            sumL[j] += Lx[j];

            float fs  = (float)s;
            float rh  = (float)(P8 + s + P4);
            float rv  = (float)(P2 + s + P6);
            float rd1 = (float)(P9 + s + P5);
            float rd2 = (float)(P3 + s + P7);
            sc += (double)(fabsf(rh - fs) + fabsf(rv - fs) + fabsf(rd1 - fs) + fabsf(rd2 - fs));
            sd += (double)(fabsf(1.0f - rh) + fabsf(1.0f - rv) + fabsf(1.0f - rd1) + fabsf(1.0f - rd2));
        }
    }
    double sb = 0.0;
    #pragma unroll
    for (int j = 0; j < 4; j++) sb += (double)sumW[j] * (double)sumL[j];

    __shared__ double sh0[RED_THREADS], sh1[RED_THREADS], sh2[RED_THREADS];
    int tt = threadIdx.x;
    sh0[tt] = sb; sh1[tt] = sc; sh2[tt] = sd;
    __syncthreads();
    for (int s2 = RED_THREADS / 2; s2 > 0; s2 >>= 1) {
        if (tt < s2) {
            sh0[tt] += sh0[tt + s2];
            sh1[tt] += sh1[tt + s2];
            sh2[tt] += sh2[tt + s2];
        }
        __syncthreads();
    }
    if (tt == 0) {
        g_part[blockIdx.x]                  = sh0[0];
        g_part[RED_BLOCKS + blockIdx.x]     = sh1[0];
        g_part[2 * RED_BLOCKS + blockIdx.x] = sh2[0];
    }
}

// ---------------------------------------------------------------------------
// Kernel 6: deterministic final sum -> scalar loss
// ---------------------------------------------------------------------------
__global__ void k_final(float* __restrict__ out)
{
    __shared__ double sh0[RED_THREADS], sh1[RED_THREADS], sh2[RED_THREADS];
    int t = threadIdx.x;
    double a = 0.0, b = 0.0, c = 0.0;
    for (int i = t; i < RED_BLOCKS; i += RED_THREADS) {
        a += g_part[i];
        b += g_part[RED_BLOCKS + i];
        c += g_part[2 * RED_BLOCKS + i];
    }
    sh0[t] = a; sh1[t] = b; sh2[t] = c;
    __syncthreads();
    for (int s2 = RED_THREADS / 2; s2 > 0; s2 >>= 1) {
        if (t < s2) {
            sh0[t] += sh0[t + s2];
            sh1[t] += sh1[t + s2];
            sh2[t] += sh2[t + s2];
        }
        __syncthreads();
    }
    if (t == 0) {
        double base = sh0[0] / (double)((double)BB * BB * HW);
        double cont = sh1[0] / (double)NPIX;
        double dirl = sh2[0] / (double)NPIX;
        out[0] = (float)(base + 0.3 * cont + 0.5 * dirl);
    }
}

// ---------------------------------------------------------------------------
extern "C" void kernel_launch(void* const* d_in, const int* in_sizes, int n_in,
                              void* d_out, int out_size)
{
    const float* pred   = (const float*)d_in[0];
    const int*   target = (const int*)d_in[1];

    k_prep<<<512, 256>>>(pred, target);
    k_thin_all<<<32, 512>>>();
    k_vscan<<<256, 256>>>();
    k_edt<<<BB * H, W>>>();
    k_reduce<<<RED_BLOCKS, RED_THREADS>>>();
    k_final<<<1, RED_THREADS>>>((float*)d_out);
}

// round 6
// speedup vs baseline: 6.7289x; 1.0594x over previous
#include <cuda_runtime.h>
#include <math.h>

// Problem constants
#define BB 4
#define H 512
#define W 512
#define HW (H*W)          // 262144
#define NPIX (BB*HW)      // 1048576
#define NSUB 32           // 32 substeps = 16 Zhang-Suen double-steps (verified exact)

typedef unsigned long long u64;
typedef unsigned int u32;

#define ONES8 0x0101010101010101ULL
#define HI8   0x8080808080808080ULL

// Static device scratch
__device__ __align__(128) u64 g_bits [BB * H * 8];   // input bitboards (1 bit/px)
__device__ __align__(128) u64 g_bits2[BB * H * 8];   // converged skeleton bits
__device__ float  g_L[NPIX];
__device__ float  g_g2[NPIX];
__device__ double g_partB[H];
__device__ int    g_partC[H];
__device__ int    g_partD[H];

// ---------------------------------------------------------------------------
// Kernel 1: log-softmax CE loss + packed argmax bitboard. 8 px/thread. MUFU.
// ---------------------------------------------------------------------------
__global__ void k_prep(const float* __restrict__ pred, const int* __restrict__ target)
{
    int t = blockIdx.x * blockDim.x + threadIdx.x;    // 0..131071
    int b = t >> 15;
    int q = t & 32767;
    int i0 = q << 3;

    const float4* p0v = (const float4*)(pred + (size_t)b * 2 * HW + i0);
    const float4* p1v = (const float4*)(pred + (size_t)b * 2 * HW + HW + i0);
    const int4*   tgv = (const int4*)(target + (size_t)b * HW + i0);
    float4 a0 = p0v[0], a1 = p0v[1];
    float4 b0 = p1v[0], b1 = p1v[1];
    int4   t0 = tgv[0], t1 = tgv[1];

    float p0a[8] = {a0.x,a0.y,a0.z,a0.w, a1.x,a1.y,a1.z,a1.w};
    float p1a[8] = {b0.x,b0.y,b0.z,b0.w, b1.x,b1.y,b1.z,b1.w};
    int   tg[8]  = {t0.x,t0.y,t0.z,t0.w, t1.x,t1.y,t1.z,t1.w};

    float Lo[8];
    u32 bits = 0;
    #pragma unroll
    for (int j = 0; j < 8; j++) {
        float p0 = p0a[j], p1 = p1a[j];
        float m   = fmaxf(p0, p1);
        float lse = m + __logf(__expf(p0 - m) + __expf(p1 - m));
        Lo[j] = lse - (tg[j] ? p1 : p0);
        bits |= (p1 > p0 ? 1u : 0u) << j;
    }
    float4* Lv = (float4*)(g_L + (size_t)b * HW + i0);
    Lv[0] = make_float4(Lo[0], Lo[1], Lo[2], Lo[3]);
    Lv[1] = make_float4(Lo[4], Lo[5], Lo[6], Lo[7]);
    ((unsigned char*)g_bits)[(size_t)b * 32768 + q] = (unsigned char)bits;
}

// ---------------------------------------------------------------------------
// Kernel 2: ALL thinning in one launch. 32 blocks = 4 images x 8 bands of 64
// rows; 32-row halo each side; one halo row consumed per substep. Bitboard
// Zhang-Suen via CSA adder tree. Writes converged PACKED bits to g_bits2.
// ---------------------------------------------------------------------------
__global__ void __launch_bounds__(512, 1) k_thin_all()
{
    __shared__ u64 buf0[128 * 8];
    __shared__ u64 buf1[128 * 8];

    int img  = blockIdx.x >> 3;
    int band = blockIdx.x & 7;
    int t    = threadIdx.x;
    const u64* gb = g_bits + (size_t)img * 4096;

    for (int i = t; i < 1024; i += 512) {
        int r   = i >> 3;
        int wx  = i & 7;
        int imr = band * 64 - 32 + r;
        buf0[i] = (imr >= 0 && imr < H) ? gb[imr * 8 + wx] : 0ULL;
    }
    __syncthreads();

    #pragma unroll 1
    for (int s = 0; s < NSUB; s++) {
        const u64* __restrict__ src = (s & 1) ? buf1 : buf0;
        u64* __restrict__ dst       = (s & 1) ? buf0 : buf1;
        bool FIRST = ((s & 1) == 0);
        int lo = s + 1, hi = 126 - s;
        int n  = (hi - lo + 1) * 8;

        for (int i = t; i < n; i += 512) {
            int r  = lo + (i >> 3);
            int wx = i & 7;
            int base = r * 8;

            u64 ctr = src[base + wx];
            u64 cW = wx      ? src[base + wx - 1] : 0ULL;
            u64 cE = wx < 7  ? src[base + wx + 1] : 0ULL;
            u64 up = src[base - 8 + wx];
            u64 uW = wx      ? src[base - 8 + wx - 1] : 0ULL;
            u64 uE = wx < 7  ? src[base - 8 + wx + 1] : 0ULL;
            u64 dn = src[base + 8 + wx];
            u64 dW = wx      ? src[base + 8 + wx - 1] : 0ULL;
            u64 dE = wx < 7  ? src[base + 8 + wx + 1] : 0ULL;

            u64 P2 = up, P6 = dn;
            u64 P4 = (ctr >> 1) | (cE << 63);
            u64 P8 = (ctr << 1) | (cW >> 63);
            u64 P3 = (up  >> 1) | (uE << 63);
            u64 P9 = (up  << 1) | (uW >> 63);
            u64 P5 = (dn  >> 1) | (dE << 63);
            u64 P7 = (dn  << 1) | (dW >> 63);

            u64 x, y;
            x = P2 ^ P3;            u64 s1a = x ^ P4;  u64 c1a = (P2 & P3) | (P4 & x);
            x = P5 ^ P6;            u64 s1b = x ^ P7;  u64 c1b = (P5 & P6) | (P7 & x);
            x = s1a ^ s1b;          u64 s1c = x ^ P8;  u64 c1c = (s1a & s1b) | (P8 & x);
            u64 s0  = s1c ^ P9;     u64 c1d = s1c & P9;
            y = c1a ^ c1b;          u64 s2a = y ^ c1c; u64 c2a = (c1a & c1b) | (c1c & y);
            u64 sl1 = s2a ^ c1d;    u64 c2b = s2a & c1d;
            u64 sl2 = c2a ^ c2b;    u64 sl3 = c2a & c2b;

            u64 ge2 = sl1 | sl2 | sl3;
            u64 ge7 = sl3 | (sl2 & sl1 & s0);
            u64 in24 = ge2 & ~ge7;

            u64 t1 = ~P2 & P3, t2 = ~P3 & P4, t3 = ~P4 & P5, t4 = ~P5 & P6;
            u64 t5 = ~P6 & P7, t6 = ~P7 & P8, t7 = ~P8 & P9, t8 = ~P9 & P2;
            u64 acc = t1, multi = 0ULL;
            multi |= acc & t2; acc |= t2;
            multi |= acc & t3; acc |= t3;
            multi |= acc & t4; acc |= t4;
            multi |= acc & t5; acc |= t5;
            multi |= acc & t6; acc |= t6;
            multi |= acc & t7; acc |= t7;
            multi |= acc & t8; acc |= t8;
            u64 eq1 = acc & ~multi;

            u64 cc;
            if (FIRST) cc = ~(P2 & P4 & P6) & ~(P4 & P6 & P8);
            else       cc = ~(P2 & P4 & P8) & ~(P2 & P6 & P8);

            u64 rem = ctr & in24 & eq1 & cc;
            dst[base + wx] = ctr ^ rem;
        }
        __syncthreads();
    }

    // write back packed band rows [32,96) of buf0 (NSUB even -> state in buf0)
    {
        int r  = 32 + (t >> 3);
        int wx = t & 7;
        int imr = band * 64 + (t >> 3);
        g_bits2[(size_t)img * 4096 + imr * 8 + wx] = buf0[r * 8 + wx];
    }
}

// ---------------------------------------------------------------------------
// Kernel 3: warp-per-column capped vertical distance from bits -> g2 = d^2.
// ---------------------------------------------------------------------------
__global__ void k_vscan()
{
    int gw   = (blockIdx.x * blockDim.x + threadIdx.x) >> 5;  // 0..2047
    int lane = threadIdx.x & 31;
    int b = gw >> 9;
    int w = gw & (W - 1);
    const u64* __restrict__ bits = g_bits2 + (size_t)b * 4096;
    float* __restrict__ g2 = g_g2 + (size_t)b * HW;
    int wx = w >> 6, bi = w & 63;

    int base_row = lane * 16;
    int v[16];
    #pragma unroll
    for (int k = 0; k < 16; k++)
        v[k] = (int)((bits[(base_row + k) * 8 + wx] >> bi) & 1ULL);

    int ll = -100000;
    #pragma unroll
    for (int k = 0; k < 16; k++) if (v[k]) ll = base_row + k;
    int incl = ll;
    #pragma unroll
    for (int o = 1; o < 32; o <<= 1) {
        int x = __shfl_up_sync(0xffffffffu, incl, o);
        if (lane >= o) incl = max(incl, x);
    }
    int prefix = __shfl_up_sync(0xffffffffu, incl, 1);
    if (lane == 0) prefix = -100000;

    int lf = 100000;
    #pragma unroll
    for (int k = 15; k >= 0; k--) if (v[k]) lf = base_row + k;
    int incl2 = lf;
    #pragma unroll
    for (int o = 1; o < 32; o <<= 1) {
        int x = __shfl_down_sync(0xffffffffu, incl2, o);
        if (lane < 32 - o) incl2 = min(incl2, x);
    }
    int suffix = __shfl_down_sync(0xffffffffu, incl2, 1);
    if (lane == 31) suffix = 100000;

    int nxt[16];
    int cur = suffix;
    #pragma unroll
    for (int k = 15; k >= 0; k--) {
        int idx = base_row + k;
        if (v[k]) cur = idx;
        nxt[k] = cur;
    }
    int last = prefix;
    #pragma unroll
    for (int k = 0; k < 16; k++) {
        int idx = base_row + k;
        if (v[k]) last = idx;
        float fd = fminf((float)(idx - last), 1024.0f);
        float bd = fminf((float)(nxt[k] - idx), 1024.0f);
        float d  = fminf(fd, bd);
        g2[idx * W + w] = d * d;
    }
}

// ---------------------------------------------------------------------------
// Kernel 4: FUSED row EDT + endpoints + broadcast base + direction convs.
// One block per image row h (512 blocks x 512 threads). For all 4 batches:
// EDT expanding search on smem g2 row -> wexp in registers, then the 3x3
// skeleton neighborhood from smem bit rows. cont/dirl are exact ints.
// ---------------------------------------------------------------------------
__global__ void __launch_bounds__(512) k_edt_reduce()
{
    __shared__ float  sg[BB][W];          // 8 KB
    __shared__ u64    sb[BB][3][8];       // 768 B
    __shared__ double shB[512];           // 4 KB
    __shared__ int    shC[512], shD[512]; // 4 KB

    int h = blockIdx.x;
    int w = threadIdx.x;

    #pragma unroll
    for (int b = 0; b < BB; b++)
        sg[b][w] = g_g2[(size_t)b * HW + h * W + w];

    if (w < 96) {
        int b  = w / 24;
        int rm = w % 24;
        int rr = rm >> 3;
        int wx = rm & 7;
        int imr = h - 1 + rr;
        sb[b][rr][wx] = (imr >= 0 && imr < H) ? g_bits2[(size_t)b * 4096 + imr * 8 + wx] : 0ULL;
    }
    __syncthreads();

    int wx = w >> 6, bi = w & 63;
    float sumW = 0.0f, sumL = 0.0f;
    int contI = 0, dirlI = 0;

    #pragma unroll
    for (int b = 0; b < BB; b++) {
        // exact expanding-search EDT for pixel (h, w)
        float d = sg[b][w];
        for (int r = 1; r < W; r++) {
            float rr = (float)(r * r);
            if (rr >= d) break;
            int ql = w - r, qr = w + r;
            if (ql >= 0) d = fminf(d, sg[b][ql] + rr);
            if (qr < W)  d = fminf(d, sg[b][qr] + rr);
        }
        float wexp = expf(sqrtf(d) * -0.05f);

        u64 um = sb[b][0][wx], cm = sb[b][1][wx], dm = sb[b][2][wx];
        int s  = (int)((cm >> bi) & 1);
        int P2 = (int)((um >> bi) & 1);
        int P6 = (int)((dm >> bi) & 1);
        int P4 = (bi < 63) ? (int)((cm >> (bi + 1)) & 1) : (wx < 7 ? (int)(sb[b][1][wx + 1] & 1) : 0);
        int P8 = (bi > 0)  ? (int)((cm >> (bi - 1)) & 1) : (wx > 0 ? (int)(sb[b][1][wx - 1] >> 63) : 0);
        int P3 = (bi < 63) ? (int)((um >> (bi + 1)) & 1) : (wx < 7 ? (int)(sb[b][0][wx + 1] & 1) : 0);
        int P9 = (bi > 0)  ? (int)((um >> (bi - 1)) & 1) : (wx > 0 ? (int)(sb[b][0][wx - 1] >> 63) : 0);
        int P5 = (bi < 63) ? (int)((dm >> (bi + 1)) & 1) : (wx < 7 ? (int)(sb[b][2][wx + 1] & 1) : 0);
        int P7 = (bi > 0)  ? (int)((dm >> (bi - 1)) & 1) : (wx > 0 ? (int)(sb[b][2][wx - 1] >> 63) : 0);

        int cnt = P2 + P3 + P4 + P5 + P6 + P7 + P8 + P9;
        float e = (s && (cnt == 1 || cnt >= 3)) ? 20.0f : 0.0f;
        sumW += wexp + e;
        sumL += g_L[(size_t)b * HW + h * W + w];

        int rh  = P8 + s + P4;
        int rv  = P2 + s + P6;
        int rd1 = P9 + s + P5;
        int rd2 = P3 + s + P7;
        contI += abs(rh - s) + abs(rv - s) + abs(rd1 - s) + abs(rd2 - s);
        dirlI += abs(1 - rh) + abs(1 - rv) + abs(1 - rd1) + abs(1 - rd2);
    }

    shB[w] = (double)sumW * (double)sumL;
    shC[w] = contI;
    shD[w] = dirlI;
    __syncthreads();
    for (int s2 = 256; s2 > 0; s2 >>= 1) {
        if (w < s2) {
            shB[w] += shB[w + s2];
            shC[w] += shC[w + s2];
            shD[w] += shD[w + s2];
        }
        __syncthreads();
    }
    if (w == 0) {
        g_partB[h] = shB[0];
        g_partC[h] = shC[0];
        g_partD[h] = shD[0];
    }
}

// ---------------------------------------------------------------------------
// Kernel 5: deterministic final sum -> scalar loss
// ---------------------------------------------------------------------------
__global__ void __launch_bounds__(512) k_final(float* __restrict__ out)
{
    __shared__ double shB[512], shC[512], shD[512];
    int t = threadIdx.x;
    shB[t] = g_partB[t];
    shC[t] = (double)g_partC[t];
    shD[t] = (double)g_partD[t];
    __syncthreads();
    for (int s2 = 256; s2 > 0; s2 >>= 1) {
        if (t < s2) {
            shB[t] += shB[t + s2];
            shC[t] += shC[t + s2];
            shD[t] += shD[t + s2];
        }
        __syncthreads();
    }
    if (t == 0) {
        double base = shB[0] / (double)((double)BB * BB * HW);   // 16*HW
        double cont = shC[0] / (double)NPIX;
        double dirl = shD[0] / (double)NPIX;
        out[0] = (float)(base + 0.3 * cont + 0.5 * dirl);
    }
}

// ---------------------------------------------------------------------------
extern "C" void kernel_launch(void* const* d_in, const int* in_sizes, int n_in,
                              void* d_out, int out_size)
{
    const float* pred   = (const float*)d_in[0];
    const int*   target = (const int*)d_in[1];

    k_prep<<<512, 256>>>(pred, target);
    k_thin_all<<<32, 512>>>();
    k_vscan<<<256, 256>>>();
    k_edt_reduce<<<H, 512>>>();
    k_final<<<1, 512>>>((float*)d_out);
}

// round 9
// speedup vs baseline: 11.6019x; 1.7242x over previous
#include <cuda_runtime.h>
#include <math.h>

// Problem constants
#define BB 4
#define H 512
#define W 512
#define HW (H*W)          // 262144
#define NPIX (BB*HW)      // 1048576
#define NSUB 32           // 32 substeps = 16 Zhang-Suen double-steps (verified exact)
#define TROWS 80          // 16-row band + 32-row halo each side
#define THIN_THREADS 640  // TROWS*8 words, 1 word/thread

typedef unsigned long long u64;
typedef unsigned int u32;

// Static device scratch
__device__ __align__(128) u64 g_bits [BB * H * 8];   // input bitboards (1 bit/px)
__device__ __align__(128) u64 g_bits2[BB * H * 8];   // converged skeleton bits
__device__ float  g_L[NPIX];
__device__ float  g_g2[NPIX];
__device__ double g_partB[H];
__device__ int    g_partC[H];
__device__ int    g_partD[H];
__device__ int    g_ctr = 0;

// ---------------------------------------------------------------------------
// Kernel 1: log-softmax CE loss + packed argmax bitboard. 8 px/thread. MUFU.
// ---------------------------------------------------------------------------
__global__ void k_prep(const float* __restrict__ pred, const int* __restrict__ target)
{
    int t = blockIdx.x * blockDim.x + threadIdx.x;    // 0..131071
    int b = t >> 15;
    int q = t & 32767;
    int i0 = q << 3;

    const float4* p0v = (const float4*)(pred + (size_t)b * 2 * HW + i0);
    const float4* p1v = (const float4*)(pred + (size_t)b * 2 * HW + HW + i0);
    const int4*   tgv = (const int4*)(target + (size_t)b * HW + i0);
    float4 a0 = p0v[0], a1 = p0v[1];
    float4 b0 = p1v[0], b1 = p1v[1];
    int4   t0 = tgv[0], t1 = tgv[1];

    float p0a[8] = {a0.x,a0.y,a0.z,a0.w, a1.x,a1.y,a1.z,a1.w};
    float p1a[8] = {b0.x,b0.y,b0.z,b0.w, b1.x,b1.y,b1.z,b1.w};
    int   tg[8]  = {t0.x,t0.y,t0.z,t0.w, t1.x,t1.y,t1.z,t1.w};

    float Lo[8];
    u32 bits = 0;
    #pragma unroll
    for (int j = 0; j < 8; j++) {
        float p0 = p0a[j], p1 = p1a[j];
        float m   = fmaxf(p0, p1);
        float lse = m + __logf(__expf(p0 - m) + __expf(p1 - m));
        Lo[j] = lse - (tg[j] ? p1 : p0);
        bits |= (p1 > p0 ? 1u : 0u) << j;
    }
    float4* Lv = (float4*)(g_L + (size_t)b * HW + i0);
    Lv[0] = make_float4(Lo[0], Lo[1], Lo[2], Lo[3]);
    Lv[1] = make_float4(Lo[4], Lo[5], Lo[6], Lo[7]);
    ((unsigned char*)g_bits)[(size_t)b * 32768 + q] = (unsigned char)bits;
}

// ---------------------------------------------------------------------------
// Kernel 2: ALL thinning in one launch. 128 blocks = 4 images x 32 bands of
// 16 rows with 32-row halos (80-row tile, 1 u64 word/thread). Row-activity
// stamps: substep s may be skipped for row r only if no change occurred in
// rows r-1..r+1 during substeps s-1 AND s-2 (then the same-parity substep
// s-2 saw the identical neighborhood and removed nothing).
// ---------------------------------------------------------------------------
__global__ void __launch_bounds__(THIN_THREADS, 1) k_thin_all()
{
    __shared__ u64 buf0[THIN_THREADS];
    __shared__ u64 buf1[THIN_THREADS];
    __shared__ int stamp[TROWS + 2];   // stampOf(r) = stamp[r+1], init 0

    int img  = blockIdx.x >> 5;
    int band = blockIdx.x & 31;
    int t    = threadIdx.x;            // 0..639
    int r    = t >> 3;
    int wx   = t & 7;
    const u64* gb = g_bits + (size_t)img * 4096;

    {
        int imr = band * 16 - 32 + r;
        u64 v = (imr >= 0 && imr < H) ? gb[imr * 8 + wx] : 0ULL;
        buf0[t] = v;
        if (r == 0 || r == TROWS - 1) buf1[t] = v;   // edge rows frozen in both buffers
        if (t < TROWS + 2) stamp[t] = 0;
    }
    __syncthreads();

    bool interior = (r >= 1 && r <= TROWS - 2);
    int base = r * 8 + wx;

    #pragma unroll 1
    for (int s = 1; s <= NSUB; s++) {
        const u64* __restrict__ src = (s & 1) ? buf0 : buf1;
        u64* __restrict__ dst       = (s & 1) ? buf1 : buf0;
        bool FIRST = (s & 1);

        if (interior) {
            int a0 = stamp[r], a1 = stamp[r + 1], a2 = stamp[r + 2];
            bool active = (max(a0, max(a1, a2)) >= s - 2);   // parity-correct skip
            if (active) {
                u64 ctr = src[base];
                u64 cW = wx      ? src[base - 1] : 0ULL;
                u64 cE = wx < 7  ? src[base + 1] : 0ULL;
                u64 up = src[base - 8];
                u64 uW = wx      ? src[base - 9] : 0ULL;
                u64 uE = wx < 7  ? src[base - 7] : 0ULL;
                u64 dn = src[base + 8];
                u64 dW = wx      ? src[base + 7] : 0ULL;
                u64 dE = wx < 7  ? src[base + 9] : 0ULL;

                u64 P2 = up, P6 = dn;
                u64 P4 = (ctr >> 1) | (cE << 63);
                u64 P8 = (ctr << 1) | (cW >> 63);
                u64 P3 = (up  >> 1) | (uE << 63);
                u64 P9 = (up  << 1) | (uW >> 63);
                u64 P5 = (dn  >> 1) | (dE << 63);
                u64 P7 = (dn  << 1) | (dW >> 63);

                u64 x, y;
                x = P2 ^ P3;            u64 s1a = x ^ P4;  u64 c1a = (P2 & P3) | (P4 & x);
                x = P5 ^ P6;            u64 s1b = x ^ P7;  u64 c1b = (P5 & P6) | (P7 & x);
                x = s1a ^ s1b;          u64 s1c = x ^ P8;  u64 c1c = (s1a & s1b) | (P8 & x);
                u64 s0  = s1c ^ P9;     u64 c1d = s1c & P9;
                y = c1a ^ c1b;          u64 s2a = y ^ c1c; u64 c2a = (c1a & c1b) | (c1c & y);
                u64 sl1 = s2a ^ c1d;    u64 c2b = s2a & c1d;
                u64 sl2 = c2a ^ c2b;    u64 sl3 = c2a & c2b;

                u64 ge2 = sl1 | sl2 | sl3;
                u64 ge7 = sl3 | (sl2 & sl1 & s0);
                u64 in24 = ge2 & ~ge7;

                u64 t1 = ~P2 & P3, t2 = ~P3 & P4, t3 = ~P4 & P5, t4 = ~P5 & P6;
                u64 t5 = ~P6 & P7, t6 = ~P7 & P8, t7 = ~P8 & P9, t8 = ~P9 & P2;
                u64 acc = t1, multi = 0ULL;
                multi |= acc & t2; acc |= t2;
                multi |= acc & t3; acc |= t3;
                multi |= acc & t4; acc |= t4;
                multi |= acc & t5; acc |= t5;
                multi |= acc & t6; acc |= t6;
                multi |= acc & t7; acc |= t7;
                multi |= acc & t8; acc |= t8;
                u64 eq1 = acc & ~multi;

                u64 cc;
                if (FIRST) cc = ~(P2 & P4 & P6) & ~(P4 & P6 & P8);
                else       cc = ~(P2 & P4 & P8) & ~(P2 & P6 & P8);

                u64 rem = ctr & in24 & eq1 & cc;
                dst[base] = ctr ^ rem;
                if (rem) stamp[r + 1] = s;   // benign race (same value)
            } else {
                dst[base] = src[base];
            }
        }
        __syncthreads();
    }

    // output band = tile rows [32,48) of buf0 (NSUB even -> state in buf0)
    if (t < 128) {
        int rr = 32 + (t >> 3);
        int ww = t & 7;
        int imr = band * 16 + (t >> 3);
        g_bits2[(size_t)img * 4096 + imr * 8 + ww] = buf0[rr * 8 + ww];
    }
}

// ---------------------------------------------------------------------------
// Kernel 3: warp-per-column capped vertical distance from bits -> g2 = d^2.
// ---------------------------------------------------------------------------
__global__ void k_vscan()
{
    int gw   = (blockIdx.x * blockDim.x + threadIdx.x) >> 5;  // 0..2047
    int lane = threadIdx.x & 31;
    int b = gw >> 9;
    int w = gw & (W - 1);
    const u64* __restrict__ bits = g_bits2 + (size_t)b * 4096;
    float* __restrict__ g2 = g_g2 + (size_t)b * HW;
    int wx = w >> 6, bi = w & 63;

    int base_row = lane * 16;
    int v[16];
    #pragma unroll
    for (int k = 0; k < 16; k++)
        v[k] = (int)((bits[(base_row + k) * 8 + wx] >> bi) & 1ULL);

    int ll = -100000;
    #pragma unroll
    for (int k = 0; k < 16; k++) if (v[k]) ll = base_row + k;
    int incl = ll;
    #pragma unroll
    for (int o = 1; o < 32; o <<= 1) {
        int x = __shfl_up_sync(0xffffffffu, incl, o);
        if (lane >= o) incl = max(incl, x);
    }
    int prefix = __shfl_up_sync(0xffffffffu, incl, 1);
    if (lane == 0) prefix = -100000;

    int lf = 100000;
    #pragma unroll
    for (int k = 15; k >= 0; k--) if (v[k]) lf = base_row + k;
    int incl2 = lf;
    #pragma unroll
    for (int o = 1; o < 32; o <<= 1) {
        int x = __shfl_down_sync(0xffffffffu, incl2, o);
        if (lane < 32 - o) incl2 = min(incl2, x);
    }
    int suffix = __shfl_down_sync(0xffffffffu, incl2, 1);
    if (lane == 31) suffix = 100000;

    int nxt[16];
    int cur = suffix;
    #pragma unroll
    for (int k = 15; k >= 0; k--) {
        int idx = base_row + k;
        if (v[k]) cur = idx;
        nxt[k] = cur;
    }
    int last = prefix;
    #pragma unroll
    for (int k = 0; k < 16; k++) {
        int idx = base_row + k;
        if (v[k]) last = idx;
        float fd = fminf((float)(idx - last), 1024.0f);
        float bd = fminf((float)(nxt[k] - idx), 1024.0f);
        float d  = fminf(fd, bd);
        g2[idx * W + w] = d * d;
    }
}

// ---------------------------------------------------------------------------
// Kernel 4: FUSED row EDT + LUT neighborhood terms + broadcast base + final
// reduction (last block). One block per image row h.
// sbW bit j = pixel j-1, so a word covers pixels -1..62: the fast 3-bit
// extract (bits bi..bi+2) is valid only for bi <= 61. bi in {62,63} uses the
// cross-word path (this was the R7/R8 bug: guard was bi<63, losing P3/P4/P5
// at every w % 64 == 62 column).
// ---------------------------------------------------------------------------
__global__ void __launch_bounds__(512) k_edt_reduce(float* __restrict__ out)
{
    __shared__ float  sg[BB][W];          // 8 KB
    __shared__ u64    sraw[BB][3][8];
    __shared__ u64    sbW[BB][3][9];      // west-shifted rows (+1 virtual word)
    __shared__ u32    lut[512];
    __shared__ double redB[16], redC[16], redD[16];
    __shared__ int    isLast;

    int h = blockIdx.x;
    int w = threadIdx.x;

    #pragma unroll
    for (int b = 0; b < BB; b++)
        sg[b][w] = g_g2[(size_t)b * HW + h * W + w];
    if (w < 96) {
        int b = w / 24, rm = w % 24, rr = rm >> 3, wx = rm & 7;
        int imr = h - 1 + rr;
        sraw[b][rr][wx] = (imr >= 0 && imr < H) ? g_bits2[(size_t)b * 4096 + imr * 8 + wx] : 0ULL;
    }
    __syncthreads();

    {   // 9-bit neighborhood LUT: bit0..2 = P9,P2,P3; 3..5 = P8,s,P4; 6..8 = P7,P6,P5
        int key = w;
        int s   = (key >> 4) & 1;
        int cnt = __popc(key) - s;
        int rh  = __popc(key & 0x38);
        int rv  = ((key >> 1) & 1) + s + ((key >> 7) & 1);
        int rd1 = (key & 1)        + s + ((key >> 8) & 1);
        int rd2 = ((key >> 2) & 1) + s + ((key >> 6) & 1);
        int dl  = abs(1 - rh) + abs(1 - rv) + abs(1 - rd1) + abs(1 - rd2);
        int e   = (s && (cnt == 1 || cnt >= 3)) ? 1 : 0;
        lut[w]  = (u32)(cnt | (dl << 4) | (e << 8));
    }
    if (w < 108) {
        int b = w / 27, rm = w % 27, rr = rm / 9, wx = rm % 9;
        u64 m = (wx < 8) ? sraw[b][rr][wx]     : 0ULL;
        u64 p = (wx > 0) ? sraw[b][rr][wx - 1] : 0ULL;
        sbW[b][rr][wx] = (m << 1) | (p >> 63);   // bit j = pixel j-1
    }
    __syncthreads();

    int wx = w >> 6, bi = w & 63;
    float sumW = 0.0f, sumL = 0.0f;
    int contI = 0, dirlI = 0;

    #pragma unroll
    for (int b = 0; b < BB; b++) {
        float d = sg[b][w];
        for (int r = 1; r < W; r++) {
            float rr = (float)(r * r);
            if (rr >= d) break;
            int ql = w - r, qr = w + r;
            if (ql >= 0) d = fminf(d, sg[b][ql] + rr);
            if (qr < W)  d = fminf(d, sg[b][qr] + rr);
        }
        float wexp = __expf(sqrtf(d) * -0.05f);

        int key;
        u64 uW = sbW[b][0][wx], cW = sbW[b][1][wx], dW = sbW[b][2][wx];
        if (bi < 62) {
            key = (int)((uW >> bi) & 7)
                | ((int)((cW >> bi) & 7) << 3)
                | ((int)((dW >> bi) & 7) << 6);
        } else {
            u64 uN = sbW[b][0][wx + 1], cN = sbW[b][1][wx + 1], dN = sbW[b][2][wx + 1];
            int sh2 = 64 - bi;   // 1 or 2
            key = (int)(((uW >> bi) | (uN << sh2)) & 7)
                | ((int)(((cW >> bi) | (cN << sh2)) & 7) << 3)
                | ((int)(((dW >> bi) | (dN << sh2)) & 7) << 6);
        }
        u32 v = lut[key];
        contI += (int)(v & 15);
        dirlI += (int)((v >> 4) & 15);
        sumW  += wexp + ((v & 256) ? 20.0f : 0.0f);
        sumL  += g_L[(size_t)b * HW + h * W + w];
    }

    double sb = (double)sumW * (double)sumL;
    unsigned fm = 0xffffffffu;
    double sc = (double)contI, sd = (double)dirlI;
    #pragma unroll
    for (int o = 16; o > 0; o >>= 1) {
        sb += __shfl_down_sync(fm, sb, o);
        sc += __shfl_down_sync(fm, sc, o);
        sd += __shfl_down_sync(fm, sd, o);
    }
    int wid = w >> 5, lane = w & 31;
    if (lane == 0) { redB[wid] = sb; redC[wid] = sc; redD[wid] = sd; }
    __syncthreads();
    if (wid == 0) {
        double b2 = (lane < 16) ? redB[lane] : 0.0;
        double c2 = (lane < 16) ? redC[lane] : 0.0;
        double d2 = (lane < 16) ? redD[lane] : 0.0;
        #pragma unroll
        for (int o = 8; o > 0; o >>= 1) {
            b2 += __shfl_down_sync(fm, b2, o);
            c2 += __shfl_down_sync(fm, c2, o);
            d2 += __shfl_down_sync(fm, d2, o);
        }
        if (lane == 0) {
            g_partB[h] = b2;
            g_partC[h] = (int)c2;
            g_partD[h] = (int)d2;
            __threadfence();
            int old = atomicAdd(&g_ctr, 1);
            isLast = (old == H - 1) ? 1 : 0;
        }
    }
    __syncthreads();

    if (isLast) {   // last block: deterministic fixed-order final sum
        __threadfence();
        double b3 = g_partB[w];
        double c3 = (double)g_partC[w];
        double d3 = (double)g_partD[w];
        #pragma unroll
        for (int o = 16; o > 0; o >>= 1) {
            b3 += __shfl_down_sync(fm, b3, o);
            c3 += __shfl_down_sync(fm, c3, o);
            d3 += __shfl_down_sync(fm, d3, o);
        }
        if (lane == 0) { redB[wid] = b3; redC[wid] = c3; redD[wid] = d3; }
        __syncthreads();
        if (wid == 0) {
            double b4 = (lane < 16) ? redB[lane] : 0.0;
            double c4 = (lane < 16) ? redC[lane] : 0.0;
            double d4 = (lane < 16) ? redD[lane] : 0.0;
            #pragma unroll
            for (int o = 8; o > 0; o >>= 1) {
                b4 += __shfl_down_sync(fm, b4, o);
                c4 += __shfl_down_sync(fm, c4, o);
                d4 += __shfl_down_sync(fm, d4, o);
            }
            if (lane == 0) {
                double base = b4 / (double)((double)BB * BB * HW);
                double cont = c4 / (double)NPIX;
                double dirl = d4 / (double)NPIX;
                out[0] = (float)(base + 0.3 * cont + 0.5 * dirl);
                g_ctr = 0;   // reset for next graph replay
            }
        }
    }
}

// ---------------------------------------------------------------------------
extern "C" void kernel_launch(void* const* d_in, const int* in_sizes, int n_in,
                              void* d_out, int out_size)
{
    const float* pred   = (const float*)d_in[0];
    const int*   target = (const int*)d_in[1];

    k_prep<<<512, 256>>>(pred, target);
    k_thin_all<<<128, THIN_THREADS>>>();
    k_vscan<<<256, 256>>>();
    k_edt_reduce<<<H, 512>>>((float*)d_out);
}

// round 10
// speedup vs baseline: 12.2950x; 1.0597x over previous
#include <cuda_runtime.h>
#include <math.h>

// Problem constants
#define BB 4
#define H 512
#define W 512
#define HW (H*W)          // 262144
#define NPIX (BB*HW)      // 1048576
#define NSUB 32           // max substeps = 16 Zhang-Suen double-steps (verified exact)
#define TROWS 80          // 16-row band + 32-row halo each side
#define THIN_THREADS 640  // TROWS*8 words, 1 word/thread

typedef unsigned long long u64;
typedef unsigned int u32;

// Static device scratch
__device__ __align__(128) u64 g_bits [BB * H * 8];   // input bitboards (1 bit/px)
__device__ __align__(128) u64 g_bits2[BB * H * 8];   // converged skeleton bits
__device__ float  g_L[NPIX];
__device__ float  g_g2[NPIX];
__device__ double g_partB[H];
__device__ int    g_partC[H];
__device__ int    g_partD[H];
__device__ int    g_ctr = 0;

// ---------------------------------------------------------------------------
// Kernel 1: log-softmax CE loss + packed argmax bitboard. 8 px/thread. MUFU.
// ---------------------------------------------------------------------------
__global__ void k_prep(const float* __restrict__ pred, const int* __restrict__ target)
{
    int t = blockIdx.x * blockDim.x + threadIdx.x;    // 0..131071
    int b = t >> 15;
    int q = t & 32767;
    int i0 = q << 3;

    const float4* p0v = (const float4*)(pred + (size_t)b * 2 * HW + i0);
    const float4* p1v = (const float4*)(pred + (size_t)b * 2 * HW + HW + i0);
    const int4*   tgv = (const int4*)(target + (size_t)b * HW + i0);
    float4 a0 = p0v[0], a1 = p0v[1];
    float4 b0 = p1v[0], b1 = p1v[1];
    int4   t0 = tgv[0], t1 = tgv[1];

    float p0a[8] = {a0.x,a0.y,a0.z,a0.w, a1.x,a1.y,a1.z,a1.w};
    float p1a[8] = {b0.x,b0.y,b0.z,b0.w, b1.x,b1.y,b1.z,b1.w};
    int   tg[8]  = {t0.x,t0.y,t0.z,t0.w, t1.x,t1.y,t1.z,t1.w};

    float Lo[8];
    u32 bits = 0;
    #pragma unroll
    for (int j = 0; j < 8; j++) {
        float p0 = p0a[j], p1 = p1a[j];
        float m   = fmaxf(p0, p1);
        float lse = m + __logf(__expf(p0 - m) + __expf(p1 - m));
        Lo[j] = lse - (tg[j] ? p1 : p0);
        bits |= (p1 > p0 ? 1u : 0u) << j;
    }
    float4* Lv = (float4*)(g_L + (size_t)b * HW + i0);
    Lv[0] = make_float4(Lo[0], Lo[1], Lo[2], Lo[3]);
    Lv[1] = make_float4(Lo[4], Lo[5], Lo[6], Lo[7]);
    ((unsigned char*)g_bits)[(size_t)b * 32768 + q] = (unsigned char)bits;
}

// ---------------------------------------------------------------------------
// Kernel 2: ALL thinning in one launch. 128 blocks = 4 images x 32 bands of
// 16 rows with 32-row halos. Row-activity stamps (skip valid iff rows r-1..r+1
// quiet through substeps s-1 AND s-2). Block-wide early exit: stamps are
// monotone, so a fully-inactive substep stays inactive forever.
// ---------------------------------------------------------------------------
__global__ void __launch_bounds__(THIN_THREADS, 1) k_thin_all()
{
    __shared__ u64 buf0[THIN_THREADS];
    __shared__ u64 buf1[THIN_THREADS];
    __shared__ int stamp[TROWS + 2];   // stampOf(r) = stamp[r+1], init 0

    int img  = blockIdx.x >> 5;
    int band = blockIdx.x & 31;
    int t    = threadIdx.x;            // 0..639
    int r    = t >> 3;
    int wx   = t & 7;
    const u64* gb = g_bits + (size_t)img * 4096;

    {
        int imr = band * 16 - 32 + r;
        u64 v = (imr >= 0 && imr < H) ? gb[imr * 8 + wx] : 0ULL;
        buf0[t] = v;
        if (r == 0 || r == TROWS - 1) buf1[t] = v;   // edge rows frozen in both buffers
        if (t < TROWS + 2) stamp[t] = 0;
    }
    __syncthreads();

    bool interior = (r >= 1 && r <= TROWS - 2);
    int base = r * 8 + wx;
    u64* fin = buf0;                   // final-state buffer (NSUB even -> buf0)

    #pragma unroll 1
    for (int s = 1; s <= NSUB; s++) {
        const u64* __restrict__ src = (s & 1) ? buf0 : buf1;
        u64* __restrict__ dst       = (s & 1) ? buf1 : buf0;
        bool FIRST = (s & 1);

        bool active = false;
        if (interior) {
            int a0 = stamp[r], a1 = stamp[r + 1], a2 = stamp[r + 2];
            active = (max(a0, max(a1, a2)) >= s - 2);   // parity-correct skip
        }
        if (!__syncthreads_or(active ? 1 : 0)) {        // whole tile converged
            fin = ((s - 1) & 1) ? buf1 : buf0;          // dst of substep s-1
            break;
        }

        if (interior) {
            if (active) {
                u64 ctr = src[base];
                u64 cW = wx      ? src[base - 1] : 0ULL;
                u64 cE = wx < 7  ? src[base + 1] : 0ULL;
                u64 up = src[base - 8];
                u64 uW = wx      ? src[base - 9] : 0ULL;
                u64 uE = wx < 7  ? src[base - 7] : 0ULL;
                u64 dn = src[base + 8];
                u64 dW = wx      ? src[base + 7] : 0ULL;
                u64 dE = wx < 7  ? src[base + 9] : 0ULL;

                u64 P2 = up, P6 = dn;
                u64 P4 = (ctr >> 1) | (cE << 63);
                u64 P8 = (ctr << 1) | (cW >> 63);
                u64 P3 = (up  >> 1) | (uE << 63);
                u64 P9 = (up  << 1) | (uW >> 63);
                u64 P5 = (dn  >> 1) | (dE << 63);
                u64 P7 = (dn  << 1) | (dW >> 63);

                u64 x, y;
                x = P2 ^ P3;            u64 s1a = x ^ P4;  u64 c1a = (P2 & P3) | (P4 & x);
                x = P5 ^ P6;            u64 s1b = x ^ P7;  u64 c1b = (P5 & P6) | (P7 & x);
                x = s1a ^ s1b;          u64 s1c = x ^ P8;  u64 c1c = (s1a & s1b) | (P8 & x);
                u64 s0  = s1c ^ P9;     u64 c1d = s1c & P9;
                y = c1a ^ c1b;          u64 s2a = y ^ c1c; u64 c2a = (c1a & c1b) | (c1c & y);
                u64 sl1 = s2a ^ c1d;    u64 c2b = s2a & c1d;
                u64 sl2 = c2a ^ c2b;    u64 sl3 = c2a & c2b;

                u64 ge2 = sl1 | sl2 | sl3;
                u64 ge7 = sl3 | (sl2 & sl1 & s0);
                u64 in24 = ge2 & ~ge7;

                u64 t1 = ~P2 & P3, t2 = ~P3 & P4, t3 = ~P4 & P5, t4 = ~P5 & P6;
                u64 t5 = ~P6 & P7, t6 = ~P7 & P8, t7 = ~P8 & P9, t8 = ~P9 & P2;
                u64 acc = t1, multi = 0ULL;
                multi |= acc & t2; acc |= t2;
                multi |= acc & t3; acc |= t3;
                multi |= acc & t4; acc |= t4;
                multi |= acc & t5; acc |= t5;
                multi |= acc & t6; acc |= t6;
                multi |= acc & t7; acc |= t7;
                multi |= acc & t8; acc |= t8;
                u64 eq1 = acc & ~multi;

                u64 cc;
                if (FIRST) cc = ~(P2 & P4 & P6) & ~(P4 & P6 & P8);
                else       cc = ~(P2 & P4 & P8) & ~(P2 & P6 & P8);

                u64 rem = ctr & in24 & eq1 & cc;
                dst[base] = ctr ^ rem;
                if (rem) stamp[r + 1] = s;   // benign race (same value)
            } else {
                dst[base] = src[base];
            }
        }
        __syncthreads();
    }

    // output band = tile rows [32,48) of fin
    if (t < 128) {
        int rr = 32 + (t >> 3);
        int ww = t & 7;
        int imr = band * 16 + (t >> 3);
        g_bits2[(size_t)img * 4096 + imr * 8 + ww] = fin[rr * 8 + ww];
    }
}

// ---------------------------------------------------------------------------
// Kernel 3: warp-per-column capped vertical distance from bits -> g2 = d^2.
// ---------------------------------------------------------------------------
__global__ void k_vscan()
{
    int gw   = (blockIdx.x * blockDim.x + threadIdx.x) >> 5;  // 0..2047
    int lane = threadIdx.x & 31;
    int b = gw >> 9;
    int w = gw & (W - 1);
    const u64* __restrict__ bits = g_bits2 + (size_t)b * 4096;
    float* __restrict__ g2 = g_g2 + (size_t)b * HW;
    int wx = w >> 6, bi = w & 63;

    int base_row = lane * 16;
    int v[16];
    #pragma unroll
    for (int k = 0; k < 16; k++)
        v[k] = (int)((bits[(base_row + k) * 8 + wx] >> bi) & 1ULL);

    int ll = -100000;
    #pragma unroll
    for (int k = 0; k < 16; k++) if (v[k]) ll = base_row + k;
    int incl = ll;
    #pragma unroll
    for (int o = 1; o < 32; o <<= 1) {
        int x = __shfl_up_sync(0xffffffffu, incl, o);
        if (lane >= o) incl = max(incl, x);
    }
    int prefix = __shfl_up_sync(0xffffffffu, incl, 1);
    if (lane == 0) prefix = -100000;

    int lf = 100000;
    #pragma unroll
    for (int k = 15; k >= 0; k--) if (v[k]) lf = base_row + k;
    int incl2 = lf;
    #pragma unroll
    for (int o = 1; o < 32; o <<= 1) {
        int x = __shfl_down_sync(0xffffffffu, incl2, o);
        if (lane < 32 - o) incl2 = min(incl2, x);
    }
    int suffix = __shfl_down_sync(0xffffffffu, incl2, 1);
    if (lane == 31) suffix = 100000;

    int nxt[16];
    int cur = suffix;
    #pragma unroll
    for (int k = 15; k >= 0; k--) {
        int idx = base_row + k;
        if (v[k]) cur = idx;
        nxt[k] = cur;
    }
    int last = prefix;
    #pragma unroll
    for (int k = 0; k < 16; k++) {
        int idx = base_row + k;
        if (v[k]) last = idx;
        float fd = fminf((float)(idx - last), 1024.0f);
        float bd = fminf((float)(nxt[k] - idx), 1024.0f);
        float d  = fminf(fd, bd);
        g2[idx * W + w] = d * d;
    }
}

// ---------------------------------------------------------------------------
// Kernel 4: FUSED row EDT (4 batches interleaved, float4 smem) + LUT
// neighborhood terms + broadcast base + last-block final reduction.
// Per-batch fmin sequence identical to the scalar version (bit-exact).
// ---------------------------------------------------------------------------
__global__ void __launch_bounds__(512) k_edt_reduce(float* __restrict__ out)
{
    __shared__ float4 sg4[W];             // 8 KB: g2 of row h, batch-interleaved
    __shared__ u64    sraw[BB][3][8];
    __shared__ u64    sbW[BB][3][9];      // west-shifted rows (+1 virtual word)
    __shared__ u32    lut[512];
    __shared__ double redB[16], redC[16], redD[16];
    __shared__ int    isLast;

    int h = blockIdx.x;
    int w = threadIdx.x;

    {
        float4 g;
        g.x = g_g2[0 * HW + h * W + w];
        g.y = g_g2[1 * HW + h * W + w];
        g.z = g_g2[2 * HW + h * W + w];
        g.w = g_g2[3 * HW + h * W + w];
        sg4[w] = g;
    }
    if (w < 96) {
        int b = w / 24, rm = w % 24, rr = rm >> 3, wx = rm & 7;
        int imr = h - 1 + rr;
        sraw[b][rr][wx] = (imr >= 0 && imr < H) ? g_bits2[(size_t)b * 4096 + imr * 8 + wx] : 0ULL;
    }
    __syncthreads();

    {   // 9-bit neighborhood LUT: bit0..2 = P9,P2,P3; 3..5 = P8,s,P4; 6..8 = P7,P6,P5
        int key = w;
        int s   = (key >> 4) & 1;
        int cnt = __popc(key) - s;
        int rh  = __popc(key & 0x38);
        int rv  = ((key >> 1) & 1) + s + ((key >> 7) & 1);
        int rd1 = (key & 1)        + s + ((key >> 8) & 1);
        int rd2 = ((key >> 2) & 1) + s + ((key >> 6) & 1);
        int dl  = abs(1 - rh) + abs(1 - rv) + abs(1 - rd1) + abs(1 - rd2);
        int e   = (s && (cnt == 1 || cnt >= 3)) ? 1 : 0;
        lut[w]  = (u32)(cnt | (dl << 4) | (e << 8));
    }
    if (w < 108) {
        int b = w / 27, rm = w % 27, rr = rm / 9, wx = rm % 9;
        u64 m = (wx < 8) ? sraw[b][rr][wx]     : 0ULL;
        u64 p = (wx > 0) ? sraw[b][rr][wx - 1] : 0ULL;
        sbW[b][rr][wx] = (m << 1) | (p >> 63);   // bit j = pixel j-1
    }
    __syncthreads();

    // ---- interleaved 4-batch expanding-search EDT ----
    float4 dd = sg4[w];
    {
        float m = fmaxf(fmaxf(dd.x, dd.y), fmaxf(dd.z, dd.w));
        for (int r = 1; r < W; r++) {
            float rr = (float)(r * r);
            if (rr >= m) break;
            int ql = w - r, qr = w + r;
            if (ql >= 0) {
                float4 v = sg4[ql];
                dd.x = fminf(dd.x, v.x + rr);
                dd.y = fminf(dd.y, v.y + rr);
                dd.z = fminf(dd.z, v.z + rr);
                dd.w = fminf(dd.w, v.w + rr);
            }
            if (qr < W) {
                float4 v = sg4[qr];
                dd.x = fminf(dd.x, v.x + rr);
                dd.y = fminf(dd.y, v.y + rr);
                dd.z = fminf(dd.z, v.z + rr);
                dd.w = fminf(dd.w, v.w + rr);
            }
            m = fmaxf(fmaxf(dd.x, dd.y), fmaxf(dd.z, dd.w));
        }
    }
    float wex[4] = { __expf(sqrtf(dd.x) * -0.05f), __expf(sqrtf(dd.y) * -0.05f),
                     __expf(sqrtf(dd.z) * -0.05f), __expf(sqrtf(dd.w) * -0.05f) };

    int wx = w >> 6, bi = w & 63;
    float sumW = 0.0f, sumL = 0.0f;
    int contI = 0, dirlI = 0;

    #pragma unroll
    for (int b = 0; b < BB; b++) {
        int key;
        u64 uW = sbW[b][0][wx], cW = sbW[b][1][wx], dW = sbW[b][2][wx];
        if (bi < 62) {
            key = (int)((uW >> bi) & 7)
                | ((int)((cW >> bi) & 7) << 3)
                | ((int)((dW >> bi) & 7) << 6);
        } else {
            u64 uN = sbW[b][0][wx + 1], cN = sbW[b][1][wx + 1], dN = sbW[b][2][wx + 1];
            int sh2 = 64 - bi;   // 1 or 2
            key = (int)(((uW >> bi) | (uN << sh2)) & 7)
                | ((int)(((cW >> bi) | (cN << sh2)) & 7) << 3)
                | ((int)(((dW >> bi) | (dN << sh2)) & 7) << 6);
        }
        u32 v = lut[key];
        contI += (int)(v & 15);
        dirlI += (int)((v >> 4) & 15);
        sumW  += wex[b] + ((v & 256) ? 20.0f : 0.0f);
        sumL  += g_L[(size_t)b * HW + h * W + w];
    }

    double sb = (double)sumW * (double)sumL;
    unsigned fm = 0xffffffffu;
    double sc = (double)contI, sd = (double)dirlI;
    #pragma unroll
    for (int o = 16; o > 0; o >>= 1) {
        sb += __shfl_down_sync(fm, sb, o);
        sc += __shfl_down_sync(fm, sc, o);
        sd += __shfl_down_sync(fm, sd, o);
    }
    int wid = w >> 5, lane = w & 31;
    if (lane == 0) { redB[wid] = sb; redC[wid] = sc; redD[wid] = sd; }
    __syncthreads();
    if (wid == 0) {
        double b2 = (lane < 16) ? redB[lane] : 0.0;
        double c2 = (lane < 16) ? redC[lane] : 0.0;
        double d2 = (lane < 16) ? redD[lane] : 0.0;
        #pragma unroll
        for (int o = 8; o > 0; o >>= 1) {
            b2 += __shfl_down_sync(fm, b2, o);
            c2 += __shfl_down_sync(fm, c2, o);
            d2 += __shfl_down_sync(fm, d2, o);
        }
        if (lane == 0) {
            g_partB[h] = b2;
            g_partC[h] = (int)c2;
            g_partD[h] = (int)d2;
            __threadfence();
            int old = atomicAdd(&g_ctr, 1);
            isLast = (old == H - 1) ? 1 : 0;
        }
    }
    __syncthreads();

    if (isLast) {   // last block: deterministic fixed-order final sum
        __threadfence();
        double b3 = g_partB[w];
        double c3 = (double)g_partC[w];
        double d3 = (double)g_partD[w];
        #pragma unroll
        for (int o = 16; o > 0; o >>= 1) {
            b3 += __shfl_down_sync(fm, b3, o);
            c3 += __shfl_down_sync(fm, c3, o);
            d3 += __shfl_down_sync(fm, d3, o);
        }
        if (lane == 0) { redB[wid] = b3; redC[wid] = c3; redD[wid] = d3; }
        __syncthreads();
        if (wid == 0) {
            double b4 = (lane < 16) ? redB[lane] : 0.0;
            double c4 = (lane < 16) ? redC[lane] : 0.0;
            double d4 = (lane < 16) ? redD[lane] : 0.0;
            #pragma unroll
            for (int o = 8; o > 0; o >>= 1) {
                b4 += __shfl_down_sync(fm, b4, o);
                c4 += __shfl_down_sync(fm, c4, o);
                d4 += __shfl_down_sync(fm, d4, o);
            }
            if (lane == 0) {
                double base = b4 / (double)((double)BB * BB * HW);
                double cont = c4 / (double)NPIX;
                double dirl = d4 / (double)NPIX;
                out[0] = (float)(base + 0.3 * cont + 0.5 * dirl);
                g_ctr = 0;   // reset for next graph replay
            }
        }
    }
}

// ---------------------------------------------------------------------------
extern "C" void kernel_launch(void* const* d_in, const int* in_sizes, int n_in,
                              void* d_out, int out_size)
{
    const float* pred   = (const float*)d_in[0];
    const int*   target = (const int*)d_in[1];

    k_prep<<<512, 256>>>(pred, target);
    k_thin_all<<<128, THIN_THREADS>>>();
    k_vscan<<<256, 256>>>();
    k_edt_reduce<<<H, 512>>>((float*)d_out);
}